// round 12
// baseline (speedup 1.0000x reference)
#include <cuda_runtime.h>
#include <cuda_bf16.h>
#include <cuda_fp16.h>
#include <math.h>
#include <stdint.h>

// Problem constants
#define B_ 2
#define T_ 2048
#define C_ 2048
#define H_ 16
#define D_ 128
#define M_ (B_ * T_)
#define ND_ (H_ * D_)
#define NX_ ((size_t)M_ * C_)
#define NW_ ((size_t)C_ * ND_)

// ---------------------------------------------------------------------------
// Scratch: bf16 hi/lo pairs (split once, use many times); V in fp16 hi/lo.
// ---------------------------------------------------------------------------
__device__ __nv_bfloat16 gx_hi[NX_],  gx_lo[NX_];
__device__ __nv_bfloat16 gwq_hi[NW_], gwq_lo[NW_];
__device__ __nv_bfloat16 gwk_hi[NW_], gwk_lo[NW_];
__device__ __nv_bfloat16 gwv_hi[NW_], gwv_lo[NW_];
__device__ __nv_bfloat16 gwo_hi[NW_], gwo_lo[NW_];
__device__ __nv_bfloat16 gq_hi[(size_t)B_ * H_ * T_ * D_], gq_lo[(size_t)B_ * H_ * T_ * D_];
__device__ __nv_bfloat16 gk_hi[(size_t)B_ * H_ * T_ * D_], gk_lo[(size_t)B_ * H_ * T_ * D_];
__device__ __half        gv_hi[(size_t)B_ * H_ * T_ * D_], gv_lo[(size_t)B_ * H_ * T_ * D_];
__device__ __nv_bfloat16 gao_hi[NX_], gao_lo[NX_];
__device__ float g_cos[T_ * (D_ / 2)];
__device__ float g_sin[T_ * (D_ / 2)];

// ---------------------------------------------------------------------------
// Helpers
// ---------------------------------------------------------------------------
__device__ __forceinline__ uint32_t smem_u32(const void* p) {
    uint32_t a;
    asm("{ .reg .u64 t; cvta.to.shared.u64 t, %1; cvt.u32.u64 %0, t; }" : "=r"(a) : "l"(p));
    return a;
}
__device__ __forceinline__ void ldsm_x4(uint32_t* r, uint32_t addr) {
    asm volatile("ldmatrix.sync.aligned.m8n8.x4.shared.b16 {%0,%1,%2,%3}, [%4];"
                 : "=r"(r[0]), "=r"(r[1]), "=r"(r[2]), "=r"(r[3]) : "r"(addr));
}
__device__ __forceinline__ void ldsm_x4_t(uint32_t* r, uint32_t addr) {
    asm volatile("ldmatrix.sync.aligned.m8n8.x4.trans.shared.b16 {%0,%1,%2,%3}, [%4];"
                 : "=r"(r[0]), "=r"(r[1]), "=r"(r[2]), "=r"(r[3]) : "r"(addr));
}
__device__ __forceinline__ void mma_bf16(float* c, const uint32_t* a, const uint32_t* b) {
    asm volatile("mma.sync.aligned.m16n8k16.row.col.f32.bf16.bf16.f32 "
                 "{%0,%1,%2,%3}, {%4,%5,%6,%7}, {%8,%9}, {%0,%1,%2,%3};"
                 : "+f"(c[0]), "+f"(c[1]), "+f"(c[2]), "+f"(c[3])
                 : "r"(a[0]), "r"(a[1]), "r"(a[2]), "r"(a[3]), "r"(b[0]), "r"(b[1]));
}
__device__ __forceinline__ void mma_f16(float* c, const uint32_t* a, const uint32_t* b) {
    asm volatile("mma.sync.aligned.m16n8k16.row.col.f32.f16.f16.f32 "
                 "{%0,%1,%2,%3}, {%4,%5,%6,%7}, {%8,%9}, {%0,%1,%2,%3};"
                 : "+f"(c[0]), "+f"(c[1]), "+f"(c[2]), "+f"(c[3])
                 : "r"(a[0]), "r"(a[1]), "r"(a[2]), "r"(a[3]), "r"(b[0]), "r"(b[1]));
}
__device__ __forceinline__ void cvt_hilo2(float x, float y, uint32_t& hi, uint32_t& lo) {
    __nv_bfloat16 hx = __float2bfloat16(x);
    __nv_bfloat16 hy = __float2bfloat16(y);
    __nv_bfloat16 lx = __float2bfloat16(x - __bfloat162float(hx));
    __nv_bfloat16 ly = __float2bfloat16(y - __bfloat162float(hy));
    hi = ((uint32_t)__bfloat16_as_ushort(hy) << 16) | __bfloat16_as_ushort(hx);
    lo = ((uint32_t)__bfloat16_as_ushort(ly) << 16) | __bfloat16_as_ushort(lx);
}
__device__ __forceinline__ void cvt_hilo2_f16(float x, float y, uint32_t& hi, uint32_t& lo) {
    __half hx = __float2half(x);
    __half hy = __float2half(y);
    __half lx = __float2half(x - __half2float(hx));
    __half ly = __float2half(y - __half2float(hy));
    hi = ((uint32_t)__half_as_ushort(hy) << 16) | __half_as_ushort(hx);
    lo = ((uint32_t)__half_as_ushort(ly) << 16) | __half_as_ushort(lx);
}
__device__ __forceinline__ uint32_t pack_f16x2(float lo, float hi) {
    uint32_t r;
    asm("cvt.rn.f16x2.f32 %0, %1, %2;" : "=r"(r) : "f"(hi), "f"(lo));
    return r;
}
__device__ __forceinline__ void cp16(uint32_t dst, const void* src) {
    asm volatile("cp.async.cg.shared.global [%0], [%1], 16;" :: "r"(dst), "l"(src));
}
__device__ __forceinline__ void cp_commit() {
    asm volatile("cp.async.commit_group;" ::: "memory");
}
template <int N>
__device__ __forceinline__ void cp_wait() {
    asm volatile("cp.async.wait_group %0;" :: "n"(N) : "memory");
}
// exp2 on the FMA pipe
__device__ __forceinline__ float exp2p(float t) {
    t = fmaxf(t, -100.0f);
    float nf = rintf(t);
    float f = t - nf;
    float p =             1.3333558146e-3f;
    p = fmaf(p, f, 9.6181291076e-3f);
    p = fmaf(p, f, 5.5504108665e-2f);
    p = fmaf(p, f, 2.4022650696e-1f);
    p = fmaf(p, f, 6.9314718056e-1f);
    p = fmaf(p, f, 1.0f);
    float sc = __int_as_float(((int)nf + 127) << 23);
    return p * sc;
}

// ---------------------------------------------------------------------------
// RoPE table + fused one-time fp32 -> bf16 hi/lo split (single launch)
// ---------------------------------------------------------------------------
__global__ void rope_table_kernel() {
    int i = blockIdx.x * blockDim.x + threadIdx.x;
    if (i >= T_ * (D_ / 2)) return;
    int t  = i >> 6;
    int d2 = i & 63;
    float inv = powf(10000.0f, -((float)(2 * d2)) / (float)D_);
    float ang = (float)t * inv;
    g_cos[i] = cosf(ang);
    g_sin[i] = sinf(ang);
}

__global__ void split_all_kernel(const float* __restrict__ x,
                                 const float* __restrict__ wq,
                                 const float* __restrict__ wk,
                                 const float* __restrict__ wv,
                                 const float* __restrict__ wo) {
    size_t idx = ((size_t)blockIdx.x * blockDim.x + threadIdx.x) * 4;
    const float* src;
    __nv_bfloat16 *hi, *lo;
    size_t base;
    if (idx < NX_) {
        src = x; hi = gx_hi; lo = gx_lo; base = idx;
    } else {
        size_t w = idx - NX_;
        int which = (int)(w >> 22);       // NW_ = 2^22
        base = w & (NW_ - 1);
        switch (which) {
            case 0:  src = wq; hi = gwq_hi; lo = gwq_lo; break;
            case 1:  src = wk; hi = gwk_hi; lo = gwk_lo; break;
            case 2:  src = wv; hi = gwv_hi; lo = gwv_lo; break;
            default: src = wo; hi = gwo_hi; lo = gwo_lo; break;
        }
    }
    float4 v = *(const float4*)(src + base);
    uint32_t h01, l01, h23, l23;
    cvt_hilo2(v.x, v.y, h01, l01);
    cvt_hilo2(v.z, v.w, h23, l23);
    *(uint2*)(hi + base) = make_uint2(h01, h23);
    *(uint2*)(lo + base) = make_uint2(l01, l23);
}

// ---------------------------------------------------------------------------
// bf16x3 GEMM, CTA tile 128x256, warp tile 64x64 (8 warps, 256 threads),
// 4-stage cp.async pipeline (wait_group<2> => 2 stages of prefetch slack),
// one __syncthreads per K-stage. LDSM:MMA ratio = 16:96 per ks (1.5x better
// than the old 64x32 warp tile).
// ---------------------------------------------------------------------------
#define ST_ALO 10240                 // A: 128 rows * 80 B
#define ST_WHI 20480
#define ST_WLO 37376                 // W: 32 rows * 528 B = 16896
#define ST_STRIDE 54272
#define GEMM_SMEM (4 * ST_STRIDE)    // 217088

template <int OP>
__global__ void __launch_bounds__(256, 1)
gemm_mma_kernel(float* __restrict__ Cout) {
    extern __shared__ char smem[];
    const uint32_t sb = smem_u32(smem);
    const int tid  = threadIdx.x;
    const int lane = tid & 31;
    const int wid  = tid >> 5;
    const int m0 = blockIdx.y * 128;
    const int n0 = blockIdx.x * 256;
    const int wm = (wid & 1) * 64;
    const int wn = (wid >> 1) * 64;

    const __nv_bfloat16 *Ahi, *Alo, *Whi, *Wlo;
    if      (OP == 0) { Ahi = gx_hi;  Alo = gx_lo;  Whi = gwq_hi; Wlo = gwq_lo; }
    else if (OP == 1) { Ahi = gx_hi;  Alo = gx_lo;  Whi = gwk_hi; Wlo = gwk_lo; }
    else if (OP == 2) { Ahi = gx_hi;  Alo = gx_lo;  Whi = gwv_hi; Wlo = gwv_lo; }
    else              { Ahi = gao_hi; Alo = gao_lo; Whi = gwo_hi; Wlo = gwo_lo; }

    float acc[4][8][4];
#pragma unroll
    for (int mt = 0; mt < 4; mt++)
#pragma unroll
        for (int nt = 0; nt < 8; nt++)
#pragma unroll
            for (int f = 0; f < 4; f++) acc[mt][nt][f] = 0.0f;

    const uint32_t a_frag = (wm + (lane & 15)) * 80 + (lane >> 4) * 16;
    const uint32_t b_frag = (lane & 15) * 528 + wn * 2 + (lane >> 4) * 16;

    auto issue = [&](int s) {
        const int k0 = s * 32;
        const uint32_t st = sb + (s & 3) * ST_STRIDE;
#pragma unroll
        for (int i = 0; i < 2; i++) {          // A: 128 rows x 64B (hi/lo)
            int c = tid + i * 256;
            int row = c >> 2, cc = c & 3;
            size_t g = (size_t)(m0 + row) * 2048 + k0 + cc * 8;
            uint32_t d = st + row * 80 + cc * 16;
            cp16(d, Ahi + g);
            cp16(d + ST_ALO, Alo + g);
        }
#pragma unroll
        for (int i = 0; i < 4; i++) {          // W: 32 rows x 512B (hi/lo)
            int c = tid + i * 256;
            int row = c >> 5, cc = c & 31;
            size_t g = (size_t)(k0 + row) * 2048 + n0 + cc * 8;
            uint32_t d = st + ST_WHI + row * 528 + cc * 16;
            cp16(d, Whi + g);
            cp16(d + (ST_WLO - ST_WHI), Wlo + g);
        }
    };

    issue(0); cp_commit();
    issue(1); cp_commit();
    issue(2); cp_commit();

    const int NS = 64;
    for (int s = 0; s < NS; s++) {
        cp_wait<2>();          // stage s complete; s+1, s+2 may be in flight
        __syncthreads();       // all warps done with the slot being recycled
        if (s + 3 < NS) issue(s + 3);
        cp_commit();           // unconditional: one group per iteration

        const uint32_t base = sb + (s & 3) * ST_STRIDE;
        const uint32_t ahi = base;
        const uint32_t alo = base + ST_ALO;
        const uint32_t whi = base + ST_WHI;
        const uint32_t wlo = base + ST_WLO;

#pragma unroll
        for (int ks = 0; ks < 2; ks++) {
            uint32_t ah[4][4], al[4][4];
#pragma unroll
            for (int mt = 0; mt < 4; mt++) {
                uint32_t ao = a_frag + mt * 1280 + ks * 32;
                ldsm_x4(ah[mt], ahi + ao);
                ldsm_x4(al[mt], alo + ao);
            }
            uint32_t bh[4][4], bl[4][4];
#pragma unroll
            for (int np = 0; np < 4; np++) {
                uint32_t bo = b_frag + ks * 8448 + np * 32;
                ldsm_x4_t(bh[np], whi + bo);
                ldsm_x4_t(bl[np], wlo + bo);
            }
#pragma unroll
            for (int mt = 0; mt < 4; mt++)
#pragma unroll
                for (int nt = 0; nt < 8; nt++)
                    mma_bf16(acc[mt][nt], ah[mt], &bh[nt >> 1][(nt & 1) * 2]);
#pragma unroll
            for (int mt = 0; mt < 4; mt++)
#pragma unroll
                for (int nt = 0; nt < 8; nt++)
                    mma_bf16(acc[mt][nt], ah[mt], &bl[nt >> 1][(nt & 1) * 2]);
#pragma unroll
            for (int mt = 0; mt < 4; mt++)
#pragma unroll
                for (int nt = 0; nt < 8; nt++)
                    mma_bf16(acc[mt][nt], al[mt], &bh[nt >> 1][(nt & 1) * 2]);
        }
    }

    // ---- epilogue (head index varies within the 256-wide N tile) ----
    const int lrow = lane >> 2;
    const int lcol = (lane & 3) * 2;
    const float QS = 0.0883883476483184405f * 1.4426950408889634f;

#pragma unroll
    for (int mt = 0; mt < 4; mt++) {
#pragma unroll
        for (int rh = 0; rh < 2; rh++) {
            const int m = m0 + wm + mt * 16 + lrow + rh * 8;
            if (OP == 3) {
                float* dst = Cout + (size_t)m * ND_;
#pragma unroll
                for (int nt = 0; nt < 8; nt++) {
                    int n = n0 + wn + nt * 8 + lcol;
                    *(float2*)(dst + n) = make_float2(acc[mt][nt][rh * 2 + 0],
                                                      acc[mt][nt][rh * 2 + 1]);
                }
            } else {
                const int b = m >> 11;
                const int t = m & (T_ - 1);
#pragma unroll
                for (int nt = 0; nt < 8; nt++) {
                    int n = n0 + wn + nt * 8 + lcol;
                    int h = n >> 7;
                    int d = n & (D_ - 1);
                    const size_t rowoff = (((size_t)(b * H_ + h) * T_ + t) << 7);
                    float x0 = acc[mt][nt][rh * 2 + 0];
                    float x1 = acc[mt][nt][rh * 2 + 1];
                    if (OP == 2) {
                        uint32_t hh, ll;
                        cvt_hilo2_f16(x0, x1, hh, ll);
                        *(uint32_t*)(gv_hi + rowoff + d) = hh;
                        *(uint32_t*)(gv_lo + rowoff + d) = ll;
                    } else {
                        float cs = g_cos[t * 64 + (d >> 1)];
                        float sn = g_sin[t * 64 + (d >> 1)];
                        float r0 = x0 * cs - x1 * sn;
                        float r1 = x0 * sn + x1 * cs;
                        if (OP == 0) { r0 *= QS; r1 *= QS; }
                        uint32_t hh, ll;
                        cvt_hilo2(r0, r1, hh, ll);
                        if (OP == 0) {
                            *(uint32_t*)(gq_hi + rowoff + d) = hh;
                            *(uint32_t*)(gq_lo + rowoff + d) = ll;
                        } else {
                            *(uint32_t*)(gk_hi + rowoff + d) = hh;
                            *(uint32_t*)(gk_lo + rowoff + d) = ll;
                        }
                    }
                }
            }
        }
    }
}

// ---------------------------------------------------------------------------
// Tensor-core flash attention: bf16x3 S, fp16 2-term PV (unchanged from R11).
// ---------------------------------------------------------------------------
#define AQ_LO 34816
#define KV_OFF 69632
#define KV_STRIDE 69632
#define KV_KLO 17408
#define KV_VHI 34816
#define KV_VLO 52224
#define ATT_SMEM 208896

__global__ void __launch_bounds__(256, 1) attn_mma_kernel() {
    extern __shared__ char smc[];
    const uint32_t sb = smem_u32(smc);
    const int tid  = threadIdx.x;
    const int lane = tid & 31;
    const int wid  = tid >> 5;
    const int bh   = blockIdx.y;
    const int b    = bh >> 4;
    const int h    = bh & (H_ - 1);
    const int qt   = (int)(gridDim.x - 1) - blockIdx.x;   // heavy tiles first
    const int q0   = qt * 128;
    const int wm   = wid * 16;
    const int lrow = lane >> 2;
    const int lcol2 = (lane & 3) * 2;

    const __nv_bfloat16* qhi = gq_hi + (size_t)bh * T_ * D_;
    const __nv_bfloat16* qlo = gq_lo + (size_t)bh * T_ * D_;
    const __nv_bfloat16* khi = gk_hi + (size_t)bh * T_ * D_;
    const __nv_bfloat16* klo = gk_lo + (size_t)bh * T_ * D_;
    const __half*        vhi = gv_hi + (size_t)bh * T_ * D_;
    const __half*        vlo = gv_lo + (size_t)bh * T_ * D_;

#pragma unroll
    for (int i = 0; i < 8; i++) {
        int c = tid + i * 256;
        int row = c >> 4, cc = c & 15;
        size_t g = (size_t)(q0 + row) * 128 + cc * 8;
        uint32_t d = sb + row * 272 + cc * 16;
        cp16(d, qhi + g);
        cp16(d + AQ_LO, qlo + g);
    }
    cp_commit();

    auto issue_kv = [&](int buf, int k0) {
        uint32_t base = sb + KV_OFF + buf * KV_STRIDE;
#pragma unroll
        for (int i = 0; i < 4; i++) {
            int c = tid + i * 256;
            int row = c >> 4, cc = c & 15;
            size_t g = (size_t)(k0 + row) * 128 + cc * 8;
            uint32_t d = base + row * 272 + cc * 16;
            cp16(d, khi + g);
            cp16(d + KV_KLO, klo + g);
            cp16(d + KV_VHI, vhi + g);
            cp16(d + KV_VLO, vlo + g);
        }
    };

    issue_kv(0, 0);
    cp_commit();

    const uint32_t aq_frag = (wm + (lane & 15)) * 272 + (lane >> 4) * 16;
    const int kb_row = (lane & 7) + ((lane >> 4) << 3);
    const uint32_t kb_frag = kb_row * 272 + ((lane >> 3) & 1) * 16;
    const uint32_t vb_frag = (lane & 15) * 272 + (lane >> 4) * 16;

    float o[16][4];
#pragma unroll
    for (int dt = 0; dt < 16; dt++)
#pragma unroll
        for (int f = 0; f < 4; f++) o[dt][f] = 0.0f;
    float m0 = -1e30f, m1 = -1e30f, l0 = 0.0f, l1 = 0.0f;

    const int njt = 2 * qt + 2;

    for (int jt = 0; jt < njt; jt++) {
        cp_wait<0>();
        __syncthreads();
        if (jt + 1 < njt) issue_kv((jt + 1) & 1, (jt + 1) * 64);
        cp_commit();

        const int k0 = jt * 64;
        if (k0 <= q0 + wm + 15) {
            const uint32_t kvb = sb + KV_OFF + (jt & 1) * KV_STRIDE;
            const uint32_t aqh = sb + aq_frag;
            const uint32_t kbh = kvb + kb_frag;
            const uint32_t vbh = kvb + KV_VHI + vb_frag;

            float s[8][4];
#pragma unroll
            for (int nt = 0; nt < 8; nt++)
#pragma unroll
                for (int f = 0; f < 4; f++) s[nt][f] = 0.0f;

#pragma unroll
            for (int ks = 0; ks < 8; ks++) {
                uint32_t ah[4], al[4];
                ldsm_x4(ah, aqh + ks * 32);
                ldsm_x4(al, aqh + AQ_LO + ks * 32);
                uint32_t kh[4][4], kl[4][4];
#pragma unroll
                for (int np = 0; np < 4; np++) {
                    uint32_t off = np * 4352 + ks * 32;
                    ldsm_x4(kh[np], kbh + off);
                    ldsm_x4(kl[np], kbh + KV_KLO + off);
                }
#pragma unroll
                for (int np = 0; np < 4; np++) {
                    mma_bf16(s[2 * np],     ah, kh[np]);
                    mma_bf16(s[2 * np + 1], ah, kh[np] + 2);
                }
#pragma unroll
                for (int np = 0; np < 4; np++) {
                    mma_bf16(s[2 * np],     ah, kl[np]);
                    mma_bf16(s[2 * np + 1], ah, kl[np] + 2);
                }
#pragma unroll
                for (int np = 0; np < 4; np++) {
                    mma_bf16(s[2 * np],     al, kh[np]);
                    mma_bf16(s[2 * np + 1], al, kh[np] + 2);
                }
            }

            if (k0 + 63 > q0 + wm) {
                const int row0 = q0 + wm + lrow;
                const int row1 = row0 + 8;
#pragma unroll
                for (int nt = 0; nt < 8; nt++) {
                    int c0 = k0 + nt * 8 + lcol2;
                    if (c0 > row0)     s[nt][0] = -1e30f;
                    if (c0 + 1 > row0) s[nt][1] = -1e30f;
                    if (c0 > row1)     s[nt][2] = -1e30f;
                    if (c0 + 1 > row1) s[nt][3] = -1e30f;
                }
            }

            float mx0 = -1e30f, mx1 = -1e30f;
#pragma unroll
            for (int nt = 0; nt < 8; nt++) {
                mx0 = fmaxf(mx0, fmaxf(s[nt][0], s[nt][1]));
                mx1 = fmaxf(mx1, fmaxf(s[nt][2], s[nt][3]));
            }
            mx0 = fmaxf(mx0, __shfl_xor_sync(0xffffffffu, mx0, 1));
            mx0 = fmaxf(mx0, __shfl_xor_sync(0xffffffffu, mx0, 2));
            mx1 = fmaxf(mx1, __shfl_xor_sync(0xffffffffu, mx1, 1));
            mx1 = fmaxf(mx1, __shfl_xor_sync(0xffffffffu, mx1, 2));
            float m0n = fmaxf(m0, mx0);
            float m1n = fmaxf(m1, mx1);
            float corr0 = exp2p(m0 - m0n);
            float corr1 = exp2p(m1 - m1n);
            m0 = m0n; m1 = m1n;

            uint32_t ph01[8], ph23[8];
            float sum0 = 0.0f, sum1 = 0.0f;
#pragma unroll
            for (int nt = 0; nt < 8; nt++) {
                float p0 = exp2p(s[nt][0] - m0);
                float p1 = exp2p(s[nt][1] - m0);
                float p2 = exp2p(s[nt][2] - m1);
                float p3 = exp2p(s[nt][3] - m1);
                sum0 += p0 + p1;
                sum1 += p2 + p3;
                ph01[nt] = pack_f16x2(p0, p1);
                ph23[nt] = pack_f16x2(p2, p3);
            }
            sum0 += __shfl_xor_sync(0xffffffffu, sum0, 1);
            sum0 += __shfl_xor_sync(0xffffffffu, sum0, 2);
            sum1 += __shfl_xor_sync(0xffffffffu, sum1, 1);
            sum1 += __shfl_xor_sync(0xffffffffu, sum1, 2);
            l0 = l0 * corr0 + sum0;
            l1 = l1 * corr1 + sum1;

#pragma unroll
            for (int dt = 0; dt < 16; dt++) {
                o[dt][0] *= corr0; o[dt][1] *= corr0;
                o[dt][2] *= corr1; o[dt][3] *= corr1;
            }

#pragma unroll
            for (int ks = 0; ks < 4; ks++) {
                uint32_t aph[4] = { ph01[2 * ks], ph23[2 * ks],
                                    ph01[2 * ks + 1], ph23[2 * ks + 1] };
#pragma unroll
                for (int half = 0; half < 2; half++) {
                    uint32_t vh[4][4], vl[4][4];
#pragma unroll
                    for (int j = 0; j < 4; j++) {
                        int np = half * 4 + j;
                        uint32_t off = ks * 4352 + np * 32;
                        ldsm_x4_t(vh[j], vbh + off);
                        ldsm_x4_t(vl[j], vbh + (KV_VLO - KV_VHI) + off);
                    }
#pragma unroll
                    for (int j = 0; j < 4; j++) {
                        int np = half * 4 + j;
                        mma_f16(o[2 * np],     aph, vh[j]);
                        mma_f16(o[2 * np + 1], aph, vh[j] + 2);
                    }
#pragma unroll
                    for (int j = 0; j < 4; j++) {
                        int np = half * 4 + j;
                        mma_f16(o[2 * np],     aph, vl[j]);
                        mma_f16(o[2 * np + 1], aph, vl[j] + 2);
                    }
                }
            }
        }
    }

    const float inv0 = 1.0f / l0;
    const float inv1 = 1.0f / l1;
    const int row0 = q0 + wm + lrow;
    const int row1 = row0 + 8;
    const size_t o0 = (size_t)(b * T_ + row0) * C_ + h * D_;
    const size_t o1 = (size_t)(b * T_ + row1) * C_ + h * D_;
#pragma unroll
    for (int dt = 0; dt < 16; dt++) {
        int d = dt * 8 + lcol2;
        uint32_t hh, ll;
        cvt_hilo2(o[dt][0] * inv0, o[dt][1] * inv0, hh, ll);
        *(uint32_t*)(gao_hi + o0 + d) = hh;
        *(uint32_t*)(gao_lo + o0 + d) = ll;
        cvt_hilo2(o[dt][2] * inv1, o[dt][3] * inv1, hh, ll);
        *(uint32_t*)(gao_hi + o1 + d) = hh;
        *(uint32_t*)(gao_lo + o1 + d) = ll;
    }
}

// ---------------------------------------------------------------------------
// Launch
// ---------------------------------------------------------------------------
extern "C" void kernel_launch(void* const* d_in, const int* in_sizes, int n_in,
                              void* d_out, int out_size) {
    const float* x  = (const float*)d_in[0];
    const float* wq = (const float*)d_in[2];
    const float* wk = (const float*)d_in[3];
    const float* wv = (const float*)d_in[4];
    const float* wo = (const float*)d_in[5];
    float* out = (float*)d_out;

    rope_table_kernel<<<(T_ * (D_ / 2) + 255) / 256, 256>>>();

    const size_t total = NX_ + 4 * NW_;
    split_all_kernel<<<(unsigned)(total / 1024), 256>>>(x, wq, wk, wv, wo);

    cudaFuncSetAttribute(gemm_mma_kernel<0>, cudaFuncAttributeMaxDynamicSharedMemorySize, GEMM_SMEM);
    cudaFuncSetAttribute(gemm_mma_kernel<1>, cudaFuncAttributeMaxDynamicSharedMemorySize, GEMM_SMEM);
    cudaFuncSetAttribute(gemm_mma_kernel<2>, cudaFuncAttributeMaxDynamicSharedMemorySize, GEMM_SMEM);
    cudaFuncSetAttribute(gemm_mma_kernel<3>, cudaFuncAttributeMaxDynamicSharedMemorySize, GEMM_SMEM);
    cudaFuncSetAttribute(attn_mma_kernel,    cudaFuncAttributeMaxDynamicSharedMemorySize, ATT_SMEM);

    dim3 gg(ND_ / 256, M_ / 128);  // (8, 32) = 256 CTAs
    gemm_mma_kernel<0><<<gg, 256, GEMM_SMEM>>>(nullptr);
    gemm_mma_kernel<1><<<gg, 256, GEMM_SMEM>>>(nullptr);
    gemm_mma_kernel<2><<<gg, 256, GEMM_SMEM>>>(nullptr);

    attn_mma_kernel<<<dim3(T_ / 128, B_ * H_), 256, ATT_SMEM>>>();

    gemm_mma_kernel<3><<<gg, 256, GEMM_SMEM>>>(out);
}

// round 13
// speedup vs baseline: 1.3648x; 1.3648x over previous
#include <cuda_runtime.h>
#include <cuda_bf16.h>
#include <cuda_fp16.h>
#include <math.h>
#include <stdint.h>

// Problem constants
#define B_ 2
#define T_ 2048
#define C_ 2048
#define H_ 16
#define D_ 128
#define M_ (B_ * T_)
#define ND_ (H_ * D_)
#define NX_ ((size_t)M_ * C_)
#define NW_ ((size_t)C_ * ND_)

// ---------------------------------------------------------------------------
// Scratch. GEMM path: A single fp16, W split fp16 hi/lo (exact).
// Attention: Q/K bf16 hi/lo (bf16x3 S), V fp16 hi/lo, gao single fp16.
// ---------------------------------------------------------------------------
__device__ __half gx[NX_];
__device__ __half gwq_hi[NW_], gwq_lo[NW_];
__device__ __half gwk_hi[NW_], gwk_lo[NW_];
__device__ __half gwv_hi[NW_], gwv_lo[NW_];
__device__ __half gwo_hi[NW_], gwo_lo[NW_];
__device__ __nv_bfloat16 gq_hi[(size_t)B_ * H_ * T_ * D_], gq_lo[(size_t)B_ * H_ * T_ * D_];
__device__ __nv_bfloat16 gk_hi[(size_t)B_ * H_ * T_ * D_], gk_lo[(size_t)B_ * H_ * T_ * D_];
__device__ __half        gv_hi[(size_t)B_ * H_ * T_ * D_], gv_lo[(size_t)B_ * H_ * T_ * D_];
__device__ __half gao[NX_];
__device__ float g_cos[T_ * (D_ / 2)];
__device__ float g_sin[T_ * (D_ / 2)];

// ---------------------------------------------------------------------------
// Helpers
// ---------------------------------------------------------------------------
__device__ __forceinline__ uint32_t smem_u32(const void* p) {
    uint32_t a;
    asm("{ .reg .u64 t; cvta.to.shared.u64 t, %1; cvt.u32.u64 %0, t; }" : "=r"(a) : "l"(p));
    return a;
}
__device__ __forceinline__ void ldsm_x4(uint32_t* r, uint32_t addr) {
    asm volatile("ldmatrix.sync.aligned.m8n8.x4.shared.b16 {%0,%1,%2,%3}, [%4];"
                 : "=r"(r[0]), "=r"(r[1]), "=r"(r[2]), "=r"(r[3]) : "r"(addr));
}
__device__ __forceinline__ void ldsm_x4_t(uint32_t* r, uint32_t addr) {
    asm volatile("ldmatrix.sync.aligned.m8n8.x4.trans.shared.b16 {%0,%1,%2,%3}, [%4];"
                 : "=r"(r[0]), "=r"(r[1]), "=r"(r[2]), "=r"(r[3]) : "r"(addr));
}
__device__ __forceinline__ void mma_bf16(float* c, const uint32_t* a, const uint32_t* b) {
    asm volatile("mma.sync.aligned.m16n8k16.row.col.f32.bf16.bf16.f32 "
                 "{%0,%1,%2,%3}, {%4,%5,%6,%7}, {%8,%9}, {%0,%1,%2,%3};"
                 : "+f"(c[0]), "+f"(c[1]), "+f"(c[2]), "+f"(c[3])
                 : "r"(a[0]), "r"(a[1]), "r"(a[2]), "r"(a[3]), "r"(b[0]), "r"(b[1]));
}
__device__ __forceinline__ void mma_f16(float* c, const uint32_t* a, const uint32_t* b) {
    asm volatile("mma.sync.aligned.m16n8k16.row.col.f32.f16.f16.f32 "
                 "{%0,%1,%2,%3}, {%4,%5,%6,%7}, {%8,%9}, {%0,%1,%2,%3};"
                 : "+f"(c[0]), "+f"(c[1]), "+f"(c[2]), "+f"(c[3])
                 : "r"(a[0]), "r"(a[1]), "r"(a[2]), "r"(a[3]), "r"(b[0]), "r"(b[1]));
}
__device__ __forceinline__ void cvt_hilo2(float x, float y, uint32_t& hi, uint32_t& lo) {
    __nv_bfloat16 hx = __float2bfloat16(x);
    __nv_bfloat16 hy = __float2bfloat16(y);
    __nv_bfloat16 lx = __float2bfloat16(x - __bfloat162float(hx));
    __nv_bfloat16 ly = __float2bfloat16(y - __bfloat162float(hy));
    hi = ((uint32_t)__bfloat16_as_ushort(hy) << 16) | __bfloat16_as_ushort(hx);
    lo = ((uint32_t)__bfloat16_as_ushort(ly) << 16) | __bfloat16_as_ushort(lx);
}
__device__ __forceinline__ void cvt_hilo2_f16(float x, float y, uint32_t& hi, uint32_t& lo) {
    __half hx = __float2half(x);
    __half hy = __float2half(y);
    __half lx = __float2half(x - __half2float(hx));
    __half ly = __float2half(y - __half2float(hy));
    hi = ((uint32_t)__half_as_ushort(hy) << 16) | __half_as_ushort(hx);
    lo = ((uint32_t)__half_as_ushort(ly) << 16) | __half_as_ushort(lx);
}
__device__ __forceinline__ uint32_t pack_f16x2(float lo, float hi) {
    uint32_t r;
    asm("cvt.rn.f16x2.f32 %0, %1, %2;" : "=r"(r) : "f"(hi), "f"(lo));
    return r;
}
__device__ __forceinline__ void cp16(uint32_t dst, const void* src) {
    asm volatile("cp.async.cg.shared.global [%0], [%1], 16;" :: "r"(dst), "l"(src));
}
__device__ __forceinline__ void cp_commit() {
    asm volatile("cp.async.commit_group;" ::: "memory");
}
template <int N>
__device__ __forceinline__ void cp_wait() {
    asm volatile("cp.async.wait_group %0;" :: "n"(N) : "memory");
}
// exp2 on the FMA pipe
__device__ __forceinline__ float exp2p(float t) {
    t = fmaxf(t, -100.0f);
    float nf = rintf(t);
    float f = t - nf;
    float p =             1.3333558146e-3f;
    p = fmaf(p, f, 9.6181291076e-3f);
    p = fmaf(p, f, 5.5504108665e-2f);
    p = fmaf(p, f, 2.4022650696e-1f);
    p = fmaf(p, f, 6.9314718056e-1f);
    p = fmaf(p, f, 1.0f);
    float sc = __int_as_float(((int)nf + 127) << 23);
    return p * sc;
}

// ---------------------------------------------------------------------------
// RoPE table + one-time input conversion: x -> fp16, weights -> fp16 hi/lo
// ---------------------------------------------------------------------------
__global__ void rope_table_kernel() {
    int i = blockIdx.x * blockDim.x + threadIdx.x;
    if (i >= T_ * (D_ / 2)) return;
    int t  = i >> 6;
    int d2 = i & 63;
    float inv = powf(10000.0f, -((float)(2 * d2)) / (float)D_);
    float ang = (float)t * inv;
    g_cos[i] = cosf(ang);
    g_sin[i] = sinf(ang);
}

__global__ void split_all_kernel(const float* __restrict__ x,
                                 const float* __restrict__ wq,
                                 const float* __restrict__ wk,
                                 const float* __restrict__ wv,
                                 const float* __restrict__ wo) {
    size_t idx = ((size_t)blockIdx.x * blockDim.x + threadIdx.x) * 4;
    if (idx < NX_) {
        float4 v = *(const float4*)(x + idx);
        *(uint2*)(gx + idx) = make_uint2(pack_f16x2(v.x, v.y), pack_f16x2(v.z, v.w));
        return;
    }
    size_t w = idx - NX_;
    int which = (int)(w >> 22);       // NW_ = 2^22
    size_t base = w & (NW_ - 1);
    const float* src;
    __half *hi, *lo;
    switch (which) {
        case 0:  src = wq; hi = gwq_hi; lo = gwq_lo; break;
        case 1:  src = wk; hi = gwk_hi; lo = gwk_lo; break;
        case 2:  src = wv; hi = gwv_hi; lo = gwv_lo; break;
        default: src = wo; hi = gwo_hi; lo = gwo_lo; break;
    }
    float4 v = *(const float4*)(src + base);
    uint32_t h01, l01, h23, l23;
    cvt_hilo2_f16(v.x, v.y, h01, l01);
    cvt_hilo2_f16(v.z, v.w, h23, l23);
    *(uint2*)(hi + base) = make_uint2(h01, h23);
    *(uint2*)(lo + base) = make_uint2(l01, l23);
}

// ---------------------------------------------------------------------------
// fp16x2 GEMM: C = A(fp16) @ (Whi + Wlo).  2 MMA terms per k-slice.
// CTA 128x128, warp 64x32, 4-stage cp.async, one __syncthreads per stage,
// 2 CTAs/SM.
// ---------------------------------------------------------------------------
#define ST_WHI 10240                 // A: 128 rows * 80 B (single fp16)
#define ST_WLO 18944                 // Whi: 32 rows * 272 B = 8704
#define ST_STRIDE 27648
#define GEMM_SMEM (4 * ST_STRIDE)    // 110592; x2 CTAs = 221184 <= 228KB

template <int OP>
__global__ void __launch_bounds__(256, 2)
gemm_mma_kernel(float* __restrict__ Cout) {
    extern __shared__ char smem[];
    const uint32_t sb = smem_u32(smem);
    const int tid  = threadIdx.x;
    const int lane = tid & 31;
    const int wid  = tid >> 5;
    const int m0 = blockIdx.y * 128;
    const int n0 = blockIdx.x * 128;
    const int wm = (wid & 1) * 64;
    const int wn = (wid >> 1) * 32;

    const __half *A, *Whi, *Wlo;
    if      (OP == 0) { A = gx;  Whi = gwq_hi; Wlo = gwq_lo; }
    else if (OP == 1) { A = gx;  Whi = gwk_hi; Wlo = gwk_lo; }
    else if (OP == 2) { A = gx;  Whi = gwv_hi; Wlo = gwv_lo; }
    else              { A = gao; Whi = gwo_hi; Wlo = gwo_lo; }

    float acc[4][4][4];
#pragma unroll
    for (int mt = 0; mt < 4; mt++)
#pragma unroll
        for (int nt = 0; nt < 4; nt++)
#pragma unroll
            for (int f = 0; f < 4; f++) acc[mt][nt][f] = 0.0f;

    const uint32_t a_frag = (wm + (lane & 15)) * 80 + (lane >> 4) * 16;
    const uint32_t b_frag = (lane & 15) * 272 + wn * 2 + (lane >> 4) * 16;

    auto issue = [&](int s) {
        const int k0 = s * 32;
        const uint32_t st = sb + (s & 3) * ST_STRIDE;
        {   // A: 128 rows x 64 B (single fp16); 512 chunks, 2 per thread
#pragma unroll
            for (int i = 0; i < 2; i++) {
                int c = tid + i * 256;
                int row = c >> 2, cc = c & 3;
                size_t g = (size_t)(m0 + row) * 2048 + k0 + cc * 8;
                cp16(st + row * 80 + cc * 16, A + g);
            }
        }
        {   // W: 32 rows x 256 B per copy; 512 chunks each, 2 per thread
#pragma unroll
            for (int i = 0; i < 2; i++) {
                int c = tid + i * 256;
                int row = c >> 4, cc = c & 15;
                size_t g = (size_t)(k0 + row) * 2048 + n0 + cc * 8;
                uint32_t d = st + ST_WHI + row * 272 + cc * 16;
                cp16(d, Whi + g);
                cp16(d + (ST_WLO - ST_WHI), Wlo + g);
            }
        }
    };

    issue(0); cp_commit();
    issue(1); cp_commit();
    issue(2); cp_commit();

    const int NS = 64;
    for (int s = 0; s < NS; s++) {
        cp_wait<2>();          // stage s complete; s+1, s+2 may be in flight
        __syncthreads();       // all warps done with the slot being recycled
        if (s + 3 < NS) issue(s + 3);
        cp_commit();           // unconditional: one group per iteration

        const uint32_t base = sb + (s & 3) * ST_STRIDE;
        const uint32_t ab  = base;
        const uint32_t whi = base + ST_WHI;
        const uint32_t wlo = base + ST_WLO;

#pragma unroll
        for (int ks = 0; ks < 2; ks++) {
            uint32_t ah[4][4];
#pragma unroll
            for (int mt = 0; mt < 4; mt++)
                ldsm_x4(ah[mt], ab + a_frag + mt * 1280 + ks * 32);
            uint32_t bh[2][4], bl[2][4];
#pragma unroll
            for (int np = 0; np < 2; np++) {
                uint32_t bo = b_frag + ks * 4352 + np * 32;
                ldsm_x4_t(bh[np], whi + bo);
                ldsm_x4_t(bl[np], wlo + bo);
            }
#pragma unroll
            for (int mt = 0; mt < 4; mt++)
#pragma unroll
                for (int nt = 0; nt < 4; nt++)
                    mma_f16(acc[mt][nt], ah[mt], &bh[nt >> 1][(nt & 1) * 2]);
#pragma unroll
            for (int mt = 0; mt < 4; mt++)
#pragma unroll
                for (int nt = 0; nt < 4; nt++)
                    mma_f16(acc[mt][nt], ah[mt], &bl[nt >> 1][(nt & 1) * 2]);
        }
    }

    // ---- epilogue ----
    const int lrow = lane >> 2;
    const int lcol = (lane & 3) * 2;
    const int h = blockIdx.x;
    const float QS = 0.0883883476483184405f * 1.4426950408889634f;

#pragma unroll
    for (int mt = 0; mt < 4; mt++) {
#pragma unroll
        for (int rh = 0; rh < 2; rh++) {
            const int m = m0 + wm + mt * 16 + lrow + rh * 8;
            if (OP == 3) {
                float* dst = Cout + (size_t)m * ND_ + n0;
#pragma unroll
                for (int nt = 0; nt < 4; nt++) {
                    int d = wn + nt * 8 + lcol;
                    *(float2*)(dst + d) = make_float2(acc[mt][nt][rh * 2 + 0],
                                                      acc[mt][nt][rh * 2 + 1]);
                }
            } else {
                const int b = m >> 11;
                const int t = m & (T_ - 1);
                const size_t rowoff = (((size_t)(b * H_ + h) * T_ + t) << 7);
                if (OP == 2) {
#pragma unroll
                    for (int nt = 0; nt < 4; nt++) {
                        int d = wn + nt * 8 + lcol;
                        uint32_t hh, ll;
                        cvt_hilo2_f16(acc[mt][nt][rh * 2 + 0], acc[mt][nt][rh * 2 + 1], hh, ll);
                        *(uint32_t*)(gv_hi + rowoff + d) = hh;
                        *(uint32_t*)(gv_lo + rowoff + d) = ll;
                    }
                } else {
                    __nv_bfloat16* dhi = (OP == 0) ? gq_hi + rowoff : gk_hi + rowoff;
                    __nv_bfloat16* dlo = (OP == 0) ? gq_lo + rowoff : gk_lo + rowoff;
#pragma unroll
                    for (int nt = 0; nt < 4; nt++) {
                        int d = wn + nt * 8 + lcol;
                        float x0 = acc[mt][nt][rh * 2 + 0];
                        float x1 = acc[mt][nt][rh * 2 + 1];
                        float cs = g_cos[t * 64 + (d >> 1)];
                        float sn = g_sin[t * 64 + (d >> 1)];
                        float r0 = x0 * cs - x1 * sn;
                        float r1 = x0 * sn + x1 * cs;
                        if (OP == 0) { r0 *= QS; r1 *= QS; }
                        uint32_t hh, ll;
                        cvt_hilo2(r0, r1, hh, ll);
                        *(uint32_t*)(dhi + d) = hh;
                        *(uint32_t*)(dlo + d) = ll;
                    }
                }
            }
        }
    }
}

// ---------------------------------------------------------------------------
// Tensor-core flash attention: bf16x3 S, fp16 2-term PV (structure from R11).
// Epilogue now writes gao as single fp16 (out-proj A input).
// ---------------------------------------------------------------------------
#define AQ_LO 34816
#define KV_OFF 69632
#define KV_STRIDE 69632
#define KV_KLO 17408
#define KV_VHI 34816
#define KV_VLO 52224
#define ATT_SMEM 208896

__global__ void __launch_bounds__(256, 1) attn_mma_kernel() {
    extern __shared__ char smc[];
    const uint32_t sb = smem_u32(smc);
    const int tid  = threadIdx.x;
    const int lane = tid & 31;
    const int wid  = tid >> 5;
    const int bh   = blockIdx.y;
    const int b    = bh >> 4;
    const int h    = bh & (H_ - 1);
    const int qt   = (int)(gridDim.x - 1) - blockIdx.x;   // heavy tiles first
    const int q0   = qt * 128;
    const int wm   = wid * 16;
    const int lrow = lane >> 2;
    const int lcol2 = (lane & 3) * 2;

    const __nv_bfloat16* qhi = gq_hi + (size_t)bh * T_ * D_;
    const __nv_bfloat16* qlo = gq_lo + (size_t)bh * T_ * D_;
    const __nv_bfloat16* khi = gk_hi + (size_t)bh * T_ * D_;
    const __nv_bfloat16* klo = gk_lo + (size_t)bh * T_ * D_;
    const __half*        vhi = gv_hi + (size_t)bh * T_ * D_;
    const __half*        vlo = gv_lo + (size_t)bh * T_ * D_;

#pragma unroll
    for (int i = 0; i < 8; i++) {
        int c = tid + i * 256;
        int row = c >> 4, cc = c & 15;
        size_t g = (size_t)(q0 + row) * 128 + cc * 8;
        uint32_t d = sb + row * 272 + cc * 16;
        cp16(d, qhi + g);
        cp16(d + AQ_LO, qlo + g);
    }
    cp_commit();

    auto issue_kv = [&](int buf, int k0) {
        uint32_t base = sb + KV_OFF + buf * KV_STRIDE;
#pragma unroll
        for (int i = 0; i < 4; i++) {
            int c = tid + i * 256;
            int row = c >> 4, cc = c & 15;
            size_t g = (size_t)(k0 + row) * 128 + cc * 8;
            uint32_t d = base + row * 272 + cc * 16;
            cp16(d, khi + g);
            cp16(d + KV_KLO, klo + g);
            cp16(d + KV_VHI, vhi + g);
            cp16(d + KV_VLO, vlo + g);
        }
    };

    issue_kv(0, 0);
    cp_commit();

    const uint32_t aq_frag = (wm + (lane & 15)) * 272 + (lane >> 4) * 16;
    const int kb_row = (lane & 7) + ((lane >> 4) << 3);
    const uint32_t kb_frag = kb_row * 272 + ((lane >> 3) & 1) * 16;
    const uint32_t vb_frag = (lane & 15) * 272 + (lane >> 4) * 16;

    float o[16][4];
#pragma unroll
    for (int dt = 0; dt < 16; dt++)
#pragma unroll
        for (int f = 0; f < 4; f++) o[dt][f] = 0.0f;
    float m0 = -1e30f, m1 = -1e30f, l0 = 0.0f, l1 = 0.0f;

    const int njt = 2 * qt + 2;

    for (int jt = 0; jt < njt; jt++) {
        cp_wait<0>();
        __syncthreads();
        if (jt + 1 < njt) issue_kv((jt + 1) & 1, (jt + 1) * 64);
        cp_commit();

        const int k0 = jt * 64;
        if (k0 <= q0 + wm + 15) {
            const uint32_t kvb = sb + KV_OFF + (jt & 1) * KV_STRIDE;
            const uint32_t aqh = sb + aq_frag;
            const uint32_t kbh = kvb + kb_frag;
            const uint32_t vbh = kvb + KV_VHI + vb_frag;

            float s[8][4];
#pragma unroll
            for (int nt = 0; nt < 8; nt++)
#pragma unroll
                for (int f = 0; f < 4; f++) s[nt][f] = 0.0f;

#pragma unroll
            for (int ks = 0; ks < 8; ks++) {
                uint32_t ah[4], al[4];
                ldsm_x4(ah, aqh + ks * 32);
                ldsm_x4(al, aqh + AQ_LO + ks * 32);
                uint32_t kh[4][4], kl[4][4];
#pragma unroll
                for (int np = 0; np < 4; np++) {
                    uint32_t off = np * 4352 + ks * 32;
                    ldsm_x4(kh[np], kbh + off);
                    ldsm_x4(kl[np], kbh + KV_KLO + off);
                }
#pragma unroll
                for (int np = 0; np < 4; np++) {
                    mma_bf16(s[2 * np],     ah, kh[np]);
                    mma_bf16(s[2 * np + 1], ah, kh[np] + 2);
                }
#pragma unroll
                for (int np = 0; np < 4; np++) {
                    mma_bf16(s[2 * np],     ah, kl[np]);
                    mma_bf16(s[2 * np + 1], ah, kl[np] + 2);
                }
#pragma unroll
                for (int np = 0; np < 4; np++) {
                    mma_bf16(s[2 * np],     al, kh[np]);
                    mma_bf16(s[2 * np + 1], al, kh[np] + 2);
                }
            }

            if (k0 + 63 > q0 + wm) {
                const int row0 = q0 + wm + lrow;
                const int row1 = row0 + 8;
#pragma unroll
                for (int nt = 0; nt < 8; nt++) {
                    int c0 = k0 + nt * 8 + lcol2;
                    if (c0 > row0)     s[nt][0] = -1e30f;
                    if (c0 + 1 > row0) s[nt][1] = -1e30f;
                    if (c0 > row1)     s[nt][2] = -1e30f;
                    if (c0 + 1 > row1) s[nt][3] = -1e30f;
                }
            }

            float mx0 = -1e30f, mx1 = -1e30f;
#pragma unroll
            for (int nt = 0; nt < 8; nt++) {
                mx0 = fmaxf(mx0, fmaxf(s[nt][0], s[nt][1]));
                mx1 = fmaxf(mx1, fmaxf(s[nt][2], s[nt][3]));
            }
            mx0 = fmaxf(mx0, __shfl_xor_sync(0xffffffffu, mx0, 1));
            mx0 = fmaxf(mx0, __shfl_xor_sync(0xffffffffu, mx0, 2));
            mx1 = fmaxf(mx1, __shfl_xor_sync(0xffffffffu, mx1, 1));
            mx1 = fmaxf(mx1, __shfl_xor_sync(0xffffffffu, mx1, 2));
            float m0n = fmaxf(m0, mx0);
            float m1n = fmaxf(m1, mx1);
            float corr0 = exp2p(m0 - m0n);
            float corr1 = exp2p(m1 - m1n);
            m0 = m0n; m1 = m1n;

            uint32_t ph01[8], ph23[8];
            float sum0 = 0.0f, sum1 = 0.0f;
#pragma unroll
            for (int nt = 0; nt < 8; nt++) {
                float p0 = exp2p(s[nt][0] - m0);
                float p1 = exp2p(s[nt][1] - m0);
                float p2 = exp2p(s[nt][2] - m1);
                float p3 = exp2p(s[nt][3] - m1);
                sum0 += p0 + p1;
                sum1 += p2 + p3;
                ph01[nt] = pack_f16x2(p0, p1);
                ph23[nt] = pack_f16x2(p2, p3);
            }
            sum0 += __shfl_xor_sync(0xffffffffu, sum0, 1);
            sum0 += __shfl_xor_sync(0xffffffffu, sum0, 2);
            sum1 += __shfl_xor_sync(0xffffffffu, sum1, 1);
            sum1 += __shfl_xor_sync(0xffffffffu, sum1, 2);
            l0 = l0 * corr0 + sum0;
            l1 = l1 * corr1 + sum1;

#pragma unroll
            for (int dt = 0; dt < 16; dt++) {
                o[dt][0] *= corr0; o[dt][1] *= corr0;
                o[dt][2] *= corr1; o[dt][3] *= corr1;
            }

#pragma unroll
            for (int ks = 0; ks < 4; ks++) {
                uint32_t aph[4] = { ph01[2 * ks], ph23[2 * ks],
                                    ph01[2 * ks + 1], ph23[2 * ks + 1] };
#pragma unroll
                for (int half = 0; half < 2; half++) {
                    uint32_t vh[4][4], vl[4][4];
#pragma unroll
                    for (int j = 0; j < 4; j++) {
                        int np = half * 4 + j;
                        uint32_t off = ks * 4352 + np * 32;
                        ldsm_x4_t(vh[j], vbh + off);
                        ldsm_x4_t(vl[j], vbh + (KV_VLO - KV_VHI) + off);
                    }
#pragma unroll
                    for (int j = 0; j < 4; j++) {
                        int np = half * 4 + j;
                        mma_f16(o[2 * np],     aph, vh[j]);
                        mma_f16(o[2 * np + 1], aph, vh[j] + 2);
                    }
#pragma unroll
                    for (int j = 0; j < 4; j++) {
                        int np = half * 4 + j;
                        mma_f16(o[2 * np],     aph, vl[j]);
                        mma_f16(o[2 * np + 1], aph, vl[j] + 2);
                    }
                }
            }
        }
    }

    // ---- epilogue: normalize, store gao as single fp16 ----
    const float inv0 = 1.0f / l0;
    const float inv1 = 1.0f / l1;
    const int row0 = q0 + wm + lrow;
    const int row1 = row0 + 8;
    const size_t o0 = (size_t)(b * T_ + row0) * C_ + h * D_;
    const size_t o1 = (size_t)(b * T_ + row1) * C_ + h * D_;
#pragma unroll
    for (int dt = 0; dt < 16; dt++) {
        int d = dt * 8 + lcol2;
        *(uint32_t*)(gao + o0 + d) = pack_f16x2(o[dt][0] * inv0, o[dt][1] * inv0);
        *(uint32_t*)(gao + o1 + d) = pack_f16x2(o[dt][2] * inv1, o[dt][3] * inv1);
    }
}

// ---------------------------------------------------------------------------
// Launch
// ---------------------------------------------------------------------------
extern "C" void kernel_launch(void* const* d_in, const int* in_sizes, int n_in,
                              void* d_out, int out_size) {
    const float* x  = (const float*)d_in[0];
    const float* wq = (const float*)d_in[2];
    const float* wk = (const float*)d_in[3];
    const float* wv = (const float*)d_in[4];
    const float* wo = (const float*)d_in[5];
    float* out = (float*)d_out;

    rope_table_kernel<<<(T_ * (D_ / 2) + 255) / 256, 256>>>();

    const size_t total = NX_ + 4 * NW_;
    split_all_kernel<<<(unsigned)(total / 1024), 256>>>(x, wq, wk, wv, wo);

    cudaFuncSetAttribute(gemm_mma_kernel<0>, cudaFuncAttributeMaxDynamicSharedMemorySize, GEMM_SMEM);
    cudaFuncSetAttribute(gemm_mma_kernel<1>, cudaFuncAttributeMaxDynamicSharedMemorySize, GEMM_SMEM);
    cudaFuncSetAttribute(gemm_mma_kernel<2>, cudaFuncAttributeMaxDynamicSharedMemorySize, GEMM_SMEM);
    cudaFuncSetAttribute(gemm_mma_kernel<3>, cudaFuncAttributeMaxDynamicSharedMemorySize, GEMM_SMEM);
    cudaFuncSetAttribute(attn_mma_kernel,    cudaFuncAttributeMaxDynamicSharedMemorySize, ATT_SMEM);

    dim3 gg(ND_ / 128, M_ / 128);  // (16, 32)
    gemm_mma_kernel<0><<<gg, 256, GEMM_SMEM>>>(nullptr);
    gemm_mma_kernel<1><<<gg, 256, GEMM_SMEM>>>(nullptr);
    gemm_mma_kernel<2><<<gg, 256, GEMM_SMEM>>>(nullptr);

    attn_mma_kernel<<<dim3(T_ / 128, B_ * H_), 256, ATT_SMEM>>>();

    gemm_mma_kernel<3><<<gg, 256, GEMM_SMEM>>>(out);
}

// round 14
// speedup vs baseline: 1.4124x; 1.0349x over previous
#include <cuda_runtime.h>
#include <cuda_bf16.h>
#include <cuda_fp16.h>
#include <math.h>
#include <stdint.h>

// Problem constants
#define B_ 2
#define T_ 2048
#define C_ 2048
#define H_ 16
#define D_ 128
#define M_ (B_ * T_)
#define ND_ (H_ * D_)
#define NX_ ((size_t)M_ * C_)
#define NW_ ((size_t)C_ * ND_)

// ---------------------------------------------------------------------------
// Scratch. GEMM path: A single fp16, W split fp16 hi/lo (exact).
// Attention: Q single fp16 (QS folded), K fp16 hi/lo, V fp16 hi/lo, gao fp16.
// ---------------------------------------------------------------------------
__device__ __half gx[NX_];
__device__ __half gwq_hi[NW_], gwq_lo[NW_];
__device__ __half gwk_hi[NW_], gwk_lo[NW_];
__device__ __half gwv_hi[NW_], gwv_lo[NW_];
__device__ __half gwo_hi[NW_], gwo_lo[NW_];
__device__ __half gq[(size_t)B_ * H_ * T_ * D_];
__device__ __half gk_hi[(size_t)B_ * H_ * T_ * D_], gk_lo[(size_t)B_ * H_ * T_ * D_];
__device__ __half gv_hi[(size_t)B_ * H_ * T_ * D_], gv_lo[(size_t)B_ * H_ * T_ * D_];
__device__ __half gao[NX_];
__device__ float g_cos[T_ * (D_ / 2)];
__device__ float g_sin[T_ * (D_ / 2)];

// ---------------------------------------------------------------------------
// Helpers
// ---------------------------------------------------------------------------
__device__ __forceinline__ uint32_t smem_u32(const void* p) {
    uint32_t a;
    asm("{ .reg .u64 t; cvta.to.shared.u64 t, %1; cvt.u32.u64 %0, t; }" : "=r"(a) : "l"(p));
    return a;
}
__device__ __forceinline__ void ldsm_x4(uint32_t* r, uint32_t addr) {
    asm volatile("ldmatrix.sync.aligned.m8n8.x4.shared.b16 {%0,%1,%2,%3}, [%4];"
                 : "=r"(r[0]), "=r"(r[1]), "=r"(r[2]), "=r"(r[3]) : "r"(addr));
}
__device__ __forceinline__ void ldsm_x4_t(uint32_t* r, uint32_t addr) {
    asm volatile("ldmatrix.sync.aligned.m8n8.x4.trans.shared.b16 {%0,%1,%2,%3}, [%4];"
                 : "=r"(r[0]), "=r"(r[1]), "=r"(r[2]), "=r"(r[3]) : "r"(addr));
}
__device__ __forceinline__ void mma_f16(float* c, const uint32_t* a, const uint32_t* b) {
    asm volatile("mma.sync.aligned.m16n8k16.row.col.f32.f16.f16.f32 "
                 "{%0,%1,%2,%3}, {%4,%5,%6,%7}, {%8,%9}, {%0,%1,%2,%3};"
                 : "+f"(c[0]), "+f"(c[1]), "+f"(c[2]), "+f"(c[3])
                 : "r"(a[0]), "r"(a[1]), "r"(a[2]), "r"(a[3]), "r"(b[0]), "r"(b[1]));
}
__device__ __forceinline__ void cvt_hilo2_f16(float x, float y, uint32_t& hi, uint32_t& lo) {
    __half hx = __float2half(x);
    __half hy = __float2half(y);
    __half lx = __float2half(x - __half2float(hx));
    __half ly = __float2half(y - __half2float(hy));
    hi = ((uint32_t)__half_as_ushort(hy) << 16) | __half_as_ushort(hx);
    lo = ((uint32_t)__half_as_ushort(ly) << 16) | __half_as_ushort(lx);
}
__device__ __forceinline__ uint32_t pack_f16x2(float lo, float hi) {
    uint32_t r;
    asm("cvt.rn.f16x2.f32 %0, %1, %2;" : "=r"(r) : "f"(hi), "f"(lo));
    return r;
}
__device__ __forceinline__ void cp16(uint32_t dst, const void* src) {
    asm volatile("cp.async.cg.shared.global [%0], [%1], 16;" :: "r"(dst), "l"(src));
}
__device__ __forceinline__ void cp_commit() {
    asm volatile("cp.async.commit_group;" ::: "memory");
}
template <int N>
__device__ __forceinline__ void cp_wait() {
    asm volatile("cp.async.wait_group %0;" :: "n"(N) : "memory");
}
// exp2 on the FMA pipe
__device__ __forceinline__ float exp2p(float t) {
    t = fmaxf(t, -100.0f);
    float nf = rintf(t);
    float f = t - nf;
    float p =             1.3333558146e-3f;
    p = fmaf(p, f, 9.6181291076e-3f);
    p = fmaf(p, f, 5.5504108665e-2f);
    p = fmaf(p, f, 2.4022650696e-1f);
    p = fmaf(p, f, 6.9314718056e-1f);
    p = fmaf(p, f, 1.0f);
    float sc = __int_as_float(((int)nf + 127) << 23);
    return p * sc;
}

// ---------------------------------------------------------------------------
// RoPE table + one-time input conversion: x -> fp16, weights -> fp16 hi/lo
// ---------------------------------------------------------------------------
__global__ void rope_table_kernel() {
    int i = blockIdx.x * blockDim.x + threadIdx.x;
    if (i >= T_ * (D_ / 2)) return;
    int t  = i >> 6;
    int d2 = i & 63;
    float inv = powf(10000.0f, -((float)(2 * d2)) / (float)D_);
    float ang = (float)t * inv;
    g_cos[i] = cosf(ang);
    g_sin[i] = sinf(ang);
}

__global__ void split_all_kernel(const float* __restrict__ x,
                                 const float* __restrict__ wq,
                                 const float* __restrict__ wk,
                                 const float* __restrict__ wv,
                                 const float* __restrict__ wo) {
    size_t idx = ((size_t)blockIdx.x * blockDim.x + threadIdx.x) * 4;
    if (idx < NX_) {
        float4 v = *(const float4*)(x + idx);
        *(uint2*)(gx + idx) = make_uint2(pack_f16x2(v.x, v.y), pack_f16x2(v.z, v.w));
        return;
    }
    size_t w = idx - NX_;
    int which = (int)(w >> 22);       // NW_ = 2^22
    size_t base = w & (NW_ - 1);
    const float* src;
    __half *hi, *lo;
    switch (which) {
        case 0:  src = wq; hi = gwq_hi; lo = gwq_lo; break;
        case 1:  src = wk; hi = gwk_hi; lo = gwk_lo; break;
        case 2:  src = wv; hi = gwv_hi; lo = gwv_lo; break;
        default: src = wo; hi = gwo_hi; lo = gwo_lo; break;
    }
    float4 v = *(const float4*)(src + base);
    uint32_t h01, l01, h23, l23;
    cvt_hilo2_f16(v.x, v.y, h01, l01);
    cvt_hilo2_f16(v.z, v.w, h23, l23);
    *(uint2*)(hi + base) = make_uint2(h01, h23);
    *(uint2*)(lo + base) = make_uint2(l01, l23);
}

// ---------------------------------------------------------------------------
// fp16x2 GEMM: C = A(fp16) @ (Whi + Wlo).  2 MMA terms per k-slice.
// CTA 128x128, warp 64x32, 4-stage cp.async, one __syncthreads per stage,
// 2 CTAs/SM. (Unchanged from R13 except Q/K epilogue targets.)
// ---------------------------------------------------------------------------
#define ST_WHI 10240                 // A: 128 rows * 80 B (single fp16)
#define ST_WLO 18944                 // Whi: 32 rows * 272 B = 8704
#define ST_STRIDE 27648
#define GEMM_SMEM (4 * ST_STRIDE)    // 110592; x2 CTAs = 221184 <= 228KB

template <int OP>
__global__ void __launch_bounds__(256, 2)
gemm_mma_kernel(float* __restrict__ Cout) {
    extern __shared__ char smem[];
    const uint32_t sb = smem_u32(smem);
    const int tid  = threadIdx.x;
    const int lane = tid & 31;
    const int wid  = tid >> 5;
    const int m0 = blockIdx.y * 128;
    const int n0 = blockIdx.x * 128;
    const int wm = (wid & 1) * 64;
    const int wn = (wid >> 1) * 32;

    const __half *A, *Whi, *Wlo;
    if      (OP == 0) { A = gx;  Whi = gwq_hi; Wlo = gwq_lo; }
    else if (OP == 1) { A = gx;  Whi = gwk_hi; Wlo = gwk_lo; }
    else if (OP == 2) { A = gx;  Whi = gwv_hi; Wlo = gwv_lo; }
    else              { A = gao; Whi = gwo_hi; Wlo = gwo_lo; }

    float acc[4][4][4];
#pragma unroll
    for (int mt = 0; mt < 4; mt++)
#pragma unroll
        for (int nt = 0; nt < 4; nt++)
#pragma unroll
            for (int f = 0; f < 4; f++) acc[mt][nt][f] = 0.0f;

    const uint32_t a_frag = (wm + (lane & 15)) * 80 + (lane >> 4) * 16;
    const uint32_t b_frag = (lane & 15) * 272 + wn * 2 + (lane >> 4) * 16;

    auto issue = [&](int s) {
        const int k0 = s * 32;
        const uint32_t st = sb + (s & 3) * ST_STRIDE;
#pragma unroll
        for (int i = 0; i < 2; i++) {
            int c = tid + i * 256;
            int row = c >> 2, cc = c & 3;
            size_t g = (size_t)(m0 + row) * 2048 + k0 + cc * 8;
            cp16(st + row * 80 + cc * 16, A + g);
        }
#pragma unroll
        for (int i = 0; i < 2; i++) {
            int c = tid + i * 256;
            int row = c >> 4, cc = c & 15;
            size_t g = (size_t)(k0 + row) * 2048 + n0 + cc * 8;
            uint32_t d = st + ST_WHI + row * 272 + cc * 16;
            cp16(d, Whi + g);
            cp16(d + (ST_WLO - ST_WHI), Wlo + g);
        }
    };

    issue(0); cp_commit();
    issue(1); cp_commit();
    issue(2); cp_commit();

    const int NS = 64;
    for (int s = 0; s < NS; s++) {
        cp_wait<2>();
        __syncthreads();
        if (s + 3 < NS) issue(s + 3);
        cp_commit();

        const uint32_t base = sb + (s & 3) * ST_STRIDE;
        const uint32_t ab  = base;
        const uint32_t whi = base + ST_WHI;
        const uint32_t wlo = base + ST_WLO;

#pragma unroll
        for (int ks = 0; ks < 2; ks++) {
            uint32_t ah[4][4];
#pragma unroll
            for (int mt = 0; mt < 4; mt++)
                ldsm_x4(ah[mt], ab + a_frag + mt * 1280 + ks * 32);
            uint32_t bh[2][4], bl[2][4];
#pragma unroll
            for (int np = 0; np < 2; np++) {
                uint32_t bo = b_frag + ks * 4352 + np * 32;
                ldsm_x4_t(bh[np], whi + bo);
                ldsm_x4_t(bl[np], wlo + bo);
            }
#pragma unroll
            for (int mt = 0; mt < 4; mt++)
#pragma unroll
                for (int nt = 0; nt < 4; nt++)
                    mma_f16(acc[mt][nt], ah[mt], &bh[nt >> 1][(nt & 1) * 2]);
#pragma unroll
            for (int mt = 0; mt < 4; mt++)
#pragma unroll
                for (int nt = 0; nt < 4; nt++)
                    mma_f16(acc[mt][nt], ah[mt], &bl[nt >> 1][(nt & 1) * 2]);
        }
    }

    // ---- epilogue ----
    const int lrow = lane >> 2;
    const int lcol = (lane & 3) * 2;
    const int h = blockIdx.x;
    const float QS = 0.0883883476483184405f * 1.4426950408889634f;

#pragma unroll
    for (int mt = 0; mt < 4; mt++) {
#pragma unroll
        for (int rh = 0; rh < 2; rh++) {
            const int m = m0 + wm + mt * 16 + lrow + rh * 8;
            if (OP == 3) {
                float* dst = Cout + (size_t)m * ND_ + n0;
#pragma unroll
                for (int nt = 0; nt < 4; nt++) {
                    int d = wn + nt * 8 + lcol;
                    *(float2*)(dst + d) = make_float2(acc[mt][nt][rh * 2 + 0],
                                                      acc[mt][nt][rh * 2 + 1]);
                }
            } else {
                const int b = m >> 11;
                const int t = m & (T_ - 1);
                const size_t rowoff = (((size_t)(b * H_ + h) * T_ + t) << 7);
                if (OP == 2) {
#pragma unroll
                    for (int nt = 0; nt < 4; nt++) {
                        int d = wn + nt * 8 + lcol;
                        uint32_t hh, ll;
                        cvt_hilo2_f16(acc[mt][nt][rh * 2 + 0], acc[mt][nt][rh * 2 + 1], hh, ll);
                        *(uint32_t*)(gv_hi + rowoff + d) = hh;
                        *(uint32_t*)(gv_lo + rowoff + d) = ll;
                    }
                } else {
#pragma unroll
                    for (int nt = 0; nt < 4; nt++) {
                        int d = wn + nt * 8 + lcol;
                        float x0 = acc[mt][nt][rh * 2 + 0];
                        float x1 = acc[mt][nt][rh * 2 + 1];
                        float cs = g_cos[t * 64 + (d >> 1)];
                        float sn = g_sin[t * 64 + (d >> 1)];
                        float r0 = x0 * cs - x1 * sn;
                        float r1 = x0 * sn + x1 * cs;
                        if (OP == 0) {
                            // Q: fold softmax scale, store single fp16
                            *(uint32_t*)(gq + rowoff + d) = pack_f16x2(r0 * QS, r1 * QS);
                        } else {
                            // K: exact fp16 hi/lo split
                            uint32_t hh, ll;
                            cvt_hilo2_f16(r0, r1, hh, ll);
                            *(uint32_t*)(gk_hi + rowoff + d) = hh;
                            *(uint32_t*)(gk_lo + rowoff + d) = ll;
                        }
                    }
                }
            }
        }
    }
}

// ---------------------------------------------------------------------------
// Tensor-core flash attention: fp16x2 S (Q single fp16, K hi/lo), fp16x2 PV.
// Heavy-first q-tile remap; warp-level skip of fully-masked tiles;
// one __syncthreads per kv-tile.
// ---------------------------------------------------------------------------
#define KV_OFF 34816                 // Q single fp16: 128 * 272 = 34816
#define KV_STRIDE 69632
#define KV_KLO 17408
#define KV_VHI 34816
#define KV_VLO 52224
#define ATT_SMEM (KV_OFF + 2 * KV_STRIDE)   // 174080

__global__ void __launch_bounds__(256, 1) attn_mma_kernel() {
    extern __shared__ char smc[];
    const uint32_t sb = smem_u32(smc);
    const int tid  = threadIdx.x;
    const int lane = tid & 31;
    const int wid  = tid >> 5;
    const int bh   = blockIdx.y;
    const int b    = bh >> 4;
    const int h    = bh & (H_ - 1);
    const int qt   = (int)(gridDim.x - 1) - blockIdx.x;   // heavy tiles first
    const int q0   = qt * 128;
    const int wm   = wid * 16;
    const int lrow = lane >> 2;
    const int lcol2 = (lane & 3) * 2;

    const __half* qg  = gq    + (size_t)bh * T_ * D_;
    const __half* khi = gk_hi + (size_t)bh * T_ * D_;
    const __half* klo = gk_lo + (size_t)bh * T_ * D_;
    const __half* vhi = gv_hi + (size_t)bh * T_ * D_;
    const __half* vlo = gv_lo + (size_t)bh * T_ * D_;

    // ---- issue Q load (single fp16) ----
#pragma unroll
    for (int i = 0; i < 8; i++) {
        int c = tid + i * 256;
        int row = c >> 4, cc = c & 15;
        size_t g = (size_t)(q0 + row) * 128 + cc * 8;
        cp16(sb + row * 272 + cc * 16, qg + g);
    }
    cp_commit();

    auto issue_kv = [&](int buf, int k0) {
        uint32_t base = sb + KV_OFF + buf * KV_STRIDE;
#pragma unroll
        for (int i = 0; i < 4; i++) {
            int c = tid + i * 256;
            int row = c >> 4, cc = c & 15;
            size_t g = (size_t)(k0 + row) * 128 + cc * 8;
            uint32_t d = base + row * 272 + cc * 16;
            cp16(d, khi + g);
            cp16(d + KV_KLO, klo + g);
            cp16(d + KV_VHI, vhi + g);
            cp16(d + KV_VLO, vlo + g);
        }
    };

    issue_kv(0, 0);
    cp_commit();

    const uint32_t aq_frag = (wm + (lane & 15)) * 272 + (lane >> 4) * 16;
    const int kb_row = (lane & 7) + ((lane >> 4) << 3);
    const uint32_t kb_frag = kb_row * 272 + ((lane >> 3) & 1) * 16;
    const uint32_t vb_frag = (lane & 15) * 272 + (lane >> 4) * 16;

    float o[16][4];
#pragma unroll
    for (int dt = 0; dt < 16; dt++)
#pragma unroll
        for (int f = 0; f < 4; f++) o[dt][f] = 0.0f;
    float m0 = -1e30f, m1 = -1e30f, l0 = 0.0f, l1 = 0.0f;

    const int njt = 2 * qt + 2;

    for (int jt = 0; jt < njt; jt++) {
        cp_wait<0>();
        __syncthreads();
        if (jt + 1 < njt) issue_kv((jt + 1) & 1, (jt + 1) * 64);
        cp_commit();

        const int k0 = jt * 64;
        if (k0 <= q0 + wm + 15) {
            const uint32_t kvb = sb + KV_OFF + (jt & 1) * KV_STRIDE;
            const uint32_t aqh = sb + aq_frag;
            const uint32_t kbh = kvb + kb_frag;
            const uint32_t vbh = kvb + KV_VHI + vb_frag;

            // ---- S = Q K^T (fp16x2: Q*(Khi + Klo)) ----
            float s[8][4];
#pragma unroll
            for (int nt = 0; nt < 8; nt++)
#pragma unroll
                for (int f = 0; f < 4; f++) s[nt][f] = 0.0f;

#pragma unroll
            for (int ks = 0; ks < 8; ks++) {
                uint32_t ah[4];
                ldsm_x4(ah, aqh + ks * 32);
                uint32_t kh[4][4], kl[4][4];
#pragma unroll
                for (int np = 0; np < 4; np++) {
                    uint32_t off = np * 4352 + ks * 32;
                    ldsm_x4(kh[np], kbh + off);
                    ldsm_x4(kl[np], kbh + KV_KLO + off);
                }
#pragma unroll
                for (int np = 0; np < 4; np++) {
                    mma_f16(s[2 * np],     ah, kh[np]);
                    mma_f16(s[2 * np + 1], ah, kh[np] + 2);
                }
#pragma unroll
                for (int np = 0; np < 4; np++) {
                    mma_f16(s[2 * np],     ah, kl[np]);
                    mma_f16(s[2 * np + 1], ah, kl[np] + 2);
                }
            }

            // ---- causal mask (diagonal tiles only) ----
            if (k0 + 63 > q0 + wm) {
                const int row0 = q0 + wm + lrow;
                const int row1 = row0 + 8;
#pragma unroll
                for (int nt = 0; nt < 8; nt++) {
                    int c0 = k0 + nt * 8 + lcol2;
                    if (c0 > row0)     s[nt][0] = -1e30f;
                    if (c0 + 1 > row0) s[nt][1] = -1e30f;
                    if (c0 > row1)     s[nt][2] = -1e30f;
                    if (c0 + 1 > row1) s[nt][3] = -1e30f;
                }
            }

            // ---- online softmax (base 2) ----
            float mx0 = -1e30f, mx1 = -1e30f;
#pragma unroll
            for (int nt = 0; nt < 8; nt++) {
                mx0 = fmaxf(mx0, fmaxf(s[nt][0], s[nt][1]));
                mx1 = fmaxf(mx1, fmaxf(s[nt][2], s[nt][3]));
            }
            mx0 = fmaxf(mx0, __shfl_xor_sync(0xffffffffu, mx0, 1));
            mx0 = fmaxf(mx0, __shfl_xor_sync(0xffffffffu, mx0, 2));
            mx1 = fmaxf(mx1, __shfl_xor_sync(0xffffffffu, mx1, 1));
            mx1 = fmaxf(mx1, __shfl_xor_sync(0xffffffffu, mx1, 2));
            float m0n = fmaxf(m0, mx0);
            float m1n = fmaxf(m1, mx1);
            float corr0 = exp2p(m0 - m0n);
            float corr1 = exp2p(m1 - m1n);
            m0 = m0n; m1 = m1n;

            uint32_t ph01[8], ph23[8];
            float sum0 = 0.0f, sum1 = 0.0f;
#pragma unroll
            for (int nt = 0; nt < 8; nt++) {
                float p0 = exp2p(s[nt][0] - m0);
                float p1 = exp2p(s[nt][1] - m0);
                float p2 = exp2p(s[nt][2] - m1);
                float p3 = exp2p(s[nt][3] - m1);
                sum0 += p0 + p1;
                sum1 += p2 + p3;
                ph01[nt] = pack_f16x2(p0, p1);
                ph23[nt] = pack_f16x2(p2, p3);
            }
            sum0 += __shfl_xor_sync(0xffffffffu, sum0, 1);
            sum0 += __shfl_xor_sync(0xffffffffu, sum0, 2);
            sum1 += __shfl_xor_sync(0xffffffffu, sum1, 1);
            sum1 += __shfl_xor_sync(0xffffffffu, sum1, 2);
            l0 = l0 * corr0 + sum0;
            l1 = l1 * corr1 + sum1;

#pragma unroll
            for (int dt = 0; dt < 16; dt++) {
                o[dt][0] *= corr0; o[dt][1] *= corr0;
                o[dt][2] *= corr1; o[dt][3] *= corr1;
            }

            // ---- O += P V (fp16x2: P*(Vhi + Vlo)) ----
#pragma unroll
            for (int ks = 0; ks < 4; ks++) {
                uint32_t aph[4] = { ph01[2 * ks], ph23[2 * ks],
                                    ph01[2 * ks + 1], ph23[2 * ks + 1] };
#pragma unroll
                for (int half = 0; half < 2; half++) {
                    uint32_t vh[4][4], vl[4][4];
#pragma unroll
                    for (int j = 0; j < 4; j++) {
                        int np = half * 4 + j;
                        uint32_t off = ks * 4352 + np * 32;
                        ldsm_x4_t(vh[j], vbh + off);
                        ldsm_x4_t(vl[j], vbh + (KV_VLO - KV_VHI) + off);
                    }
#pragma unroll
                    for (int j = 0; j < 4; j++) {
                        int np = half * 4 + j;
                        mma_f16(o[2 * np],     aph, vh[j]);
                        mma_f16(o[2 * np + 1], aph, vh[j] + 2);
                    }
#pragma unroll
                    for (int j = 0; j < 4; j++) {
                        int np = half * 4 + j;
                        mma_f16(o[2 * np],     aph, vl[j]);
                        mma_f16(o[2 * np + 1], aph, vl[j] + 2);
                    }
                }
            }
        }
    }

    // ---- epilogue: normalize, store gao as single fp16 ----
    const float inv0 = 1.0f / l0;
    const float inv1 = 1.0f / l1;
    const int row0 = q0 + wm + lrow;
    const int row1 = row0 + 8;
    const size_t o0 = (size_t)(b * T_ + row0) * C_ + h * D_;
    const size_t o1 = (size_t)(b * T_ + row1) * C_ + h * D_;
#pragma unroll
    for (int dt = 0; dt < 16; dt++) {
        int d = dt * 8 + lcol2;
        *(uint32_t*)(gao + o0 + d) = pack_f16x2(o[dt][0] * inv0, o[dt][1] * inv0);
        *(uint32_t*)(gao + o1 + d) = pack_f16x2(o[dt][2] * inv1, o[dt][3] * inv1);
    }
}

// ---------------------------------------------------------------------------
// Launch
// ---------------------------------------------------------------------------
extern "C" void kernel_launch(void* const* d_in, const int* in_sizes, int n_in,
                              void* d_out, int out_size) {
    const float* x  = (const float*)d_in[0];
    const float* wq = (const float*)d_in[2];
    const float* wk = (const float*)d_in[3];
    const float* wv = (const float*)d_in[4];
    const float* wo = (const float*)d_in[5];
    float* out = (float*)d_out;

    rope_table_kernel<<<(T_ * (D_ / 2) + 255) / 256, 256>>>();

    const size_t total = NX_ + 4 * NW_;
    split_all_kernel<<<(unsigned)(total / 1024), 256>>>(x, wq, wk, wv, wo);

    cudaFuncSetAttribute(gemm_mma_kernel<0>, cudaFuncAttributeMaxDynamicSharedMemorySize, GEMM_SMEM);
    cudaFuncSetAttribute(gemm_mma_kernel<1>, cudaFuncAttributeMaxDynamicSharedMemorySize, GEMM_SMEM);
    cudaFuncSetAttribute(gemm_mma_kernel<2>, cudaFuncAttributeMaxDynamicSharedMemorySize, GEMM_SMEM);
    cudaFuncSetAttribute(gemm_mma_kernel<3>, cudaFuncAttributeMaxDynamicSharedMemorySize, GEMM_SMEM);
    cudaFuncSetAttribute(attn_mma_kernel,    cudaFuncAttributeMaxDynamicSharedMemorySize, ATT_SMEM);

    dim3 gg(ND_ / 128, M_ / 128);  // (16, 32)
    gemm_mma_kernel<0><<<gg, 256, GEMM_SMEM>>>(nullptr);
    gemm_mma_kernel<1><<<gg, 256, GEMM_SMEM>>>(nullptr);
    gemm_mma_kernel<2><<<gg, 256, GEMM_SMEM>>>(nullptr);

    attn_mma_kernel<<<dim3(T_ / 128, B_ * H_), 256, ATT_SMEM>>>();

    gemm_mma_kernel<3><<<gg, 256, GEMM_SMEM>>>(out);
}

// round 15
// speedup vs baseline: 2.0017x; 1.4172x over previous
#include <cuda_runtime.h>
#include <cuda_bf16.h>
#include <cuda_fp16.h>
#include <math.h>
#include <stdint.h>

// Problem constants
#define B_ 2
#define T_ 2048
#define C_ 2048
#define H_ 16
#define D_ 128
#define M_ (B_ * T_)
#define ND_ (H_ * D_)
#define NX_ ((size_t)M_ * C_)
#define NW_ ((size_t)C_ * ND_)

// ---------------------------------------------------------------------------
// Scratch. GEMM path: A and W single fp16 (1-term).
// Attention: Q single fp16 (QS folded), K fp16 hi/lo, V fp16 hi/lo, gao fp16.
// ---------------------------------------------------------------------------
__device__ __half gx[NX_];
__device__ __half gwq[NW_], gwk[NW_], gwv[NW_], gwo[NW_];
__device__ __half gq[(size_t)B_ * H_ * T_ * D_];
__device__ __half gk_hi[(size_t)B_ * H_ * T_ * D_], gk_lo[(size_t)B_ * H_ * T_ * D_];
__device__ __half gv_hi[(size_t)B_ * H_ * T_ * D_], gv_lo[(size_t)B_ * H_ * T_ * D_];
__device__ __half gao[NX_];
__device__ float g_cos[T_ * (D_ / 2)];
__device__ float g_sin[T_ * (D_ / 2)];

// ---------------------------------------------------------------------------
// Helpers
// ---------------------------------------------------------------------------
__device__ __forceinline__ uint32_t smem_u32(const void* p) {
    uint32_t a;
    asm("{ .reg .u64 t; cvta.to.shared.u64 t, %1; cvt.u32.u64 %0, t; }" : "=r"(a) : "l"(p));
    return a;
}
__device__ __forceinline__ void ldsm_x4(uint32_t* r, uint32_t addr) {
    asm volatile("ldmatrix.sync.aligned.m8n8.x4.shared.b16 {%0,%1,%2,%3}, [%4];"
                 : "=r"(r[0]), "=r"(r[1]), "=r"(r[2]), "=r"(r[3]) : "r"(addr));
}
__device__ __forceinline__ void ldsm_x4_t(uint32_t* r, uint32_t addr) {
    asm volatile("ldmatrix.sync.aligned.m8n8.x4.trans.shared.b16 {%0,%1,%2,%3}, [%4];"
                 : "=r"(r[0]), "=r"(r[1]), "=r"(r[2]), "=r"(r[3]) : "r"(addr));
}
__device__ __forceinline__ void mma_f16(float* c, const uint32_t* a, const uint32_t* b) {
    asm volatile("mma.sync.aligned.m16n8k16.row.col.f32.f16.f16.f32 "
                 "{%0,%1,%2,%3}, {%4,%5,%6,%7}, {%8,%9}, {%0,%1,%2,%3};"
                 : "+f"(c[0]), "+f"(c[1]), "+f"(c[2]), "+f"(c[3])
                 : "r"(a[0]), "r"(a[1]), "r"(a[2]), "r"(a[3]), "r"(b[0]), "r"(b[1]));
}
__device__ __forceinline__ void cvt_hilo2_f16(float x, float y, uint32_t& hi, uint32_t& lo) {
    __half hx = __float2half(x);
    __half hy = __float2half(y);
    __half lx = __float2half(x - __half2float(hx));
    __half ly = __float2half(y - __half2float(hy));
    hi = ((uint32_t)__half_as_ushort(hy) << 16) | __half_as_ushort(hx);
    lo = ((uint32_t)__half_as_ushort(ly) << 16) | __half_as_ushort(lx);
}
__device__ __forceinline__ uint32_t pack_f16x2(float lo, float hi) {
    uint32_t r;
    asm("cvt.rn.f16x2.f32 %0, %1, %2;" : "=r"(r) : "f"(hi), "f"(lo));
    return r;
}
__device__ __forceinline__ void cp16(uint32_t dst, const void* src) {
    asm volatile("cp.async.cg.shared.global [%0], [%1], 16;" :: "r"(dst), "l"(src));
}
__device__ __forceinline__ void cp_commit() {
    asm volatile("cp.async.commit_group;" ::: "memory");
}
template <int N>
__device__ __forceinline__ void cp_wait() {
    asm volatile("cp.async.wait_group %0;" :: "n"(N) : "memory");
}
// exp2 on the FMA pipe
__device__ __forceinline__ float exp2p(float t) {
    t = fmaxf(t, -100.0f);
    float nf = rintf(t);
    float f = t - nf;
    float p =             1.3333558146e-3f;
    p = fmaf(p, f, 9.6181291076e-3f);
    p = fmaf(p, f, 5.5504108665e-2f);
    p = fmaf(p, f, 2.4022650696e-1f);
    p = fmaf(p, f, 6.9314718056e-1f);
    p = fmaf(p, f, 1.0f);
    float sc = __int_as_float(((int)nf + 127) << 23);
    return p * sc;
}

// ---------------------------------------------------------------------------
// RoPE table + one-time input conversion: x, weights -> single fp16
// ---------------------------------------------------------------------------
__global__ void rope_table_kernel() {
    int i = blockIdx.x * blockDim.x + threadIdx.x;
    if (i >= T_ * (D_ / 2)) return;
    int t  = i >> 6;
    int d2 = i & 63;
    float inv = powf(10000.0f, -((float)(2 * d2)) / (float)D_);
    float ang = (float)t * inv;
    g_cos[i] = cosf(ang);
    g_sin[i] = sinf(ang);
}

__global__ void split_all_kernel(const float* __restrict__ x,
                                 const float* __restrict__ wq,
                                 const float* __restrict__ wk,
                                 const float* __restrict__ wv,
                                 const float* __restrict__ wo) {
    size_t idx = ((size_t)blockIdx.x * blockDim.x + threadIdx.x) * 4;
    const float* src;
    __half* dst;
    size_t base;
    if (idx < NX_) {
        src = x; dst = gx; base = idx;
    } else {
        size_t w = idx - NX_;
        int which = (int)(w >> 22);       // NW_ = 2^22
        base = w & (NW_ - 1);
        switch (which) {
            case 0:  src = wq; dst = gwq; break;
            case 1:  src = wk; dst = gwk; break;
            case 2:  src = wv; dst = gwv; break;
            default: src = wo; dst = gwo; break;
        }
    }
    float4 v = *(const float4*)(src + base);
    *(uint2*)(dst + base) = make_uint2(pack_f16x2(v.x, v.y), pack_f16x2(v.z, v.w));
}

// ---------------------------------------------------------------------------
// 1-term fp16 GEMM: C = A(fp16) @ W(fp16), fp32 accumulate.
// CTA 128x128, warp 64x32, 4-stage cp.async, one __syncthreads per stage,
// 2 CTAs/SM.
// ---------------------------------------------------------------------------
#define ST_W 10240                   // A: 128 rows * 80 B
#define ST_STRIDE 18944              // + W: 32 rows * 272 B = 8704
#define GEMM_SMEM (4 * ST_STRIDE)    // 75776; x2 CTAs = 151552

template <int OP>
__global__ void __launch_bounds__(256, 2)
gemm_mma_kernel(float* __restrict__ Cout) {
    extern __shared__ char smem[];
    const uint32_t sb = smem_u32(smem);
    const int tid  = threadIdx.x;
    const int lane = tid & 31;
    const int wid  = tid >> 5;
    const int m0 = blockIdx.y * 128;
    const int n0 = blockIdx.x * 128;
    const int wm = (wid & 1) * 64;
    const int wn = (wid >> 1) * 32;

    const __half *A, *W;
    if      (OP == 0) { A = gx;  W = gwq; }
    else if (OP == 1) { A = gx;  W = gwk; }
    else if (OP == 2) { A = gx;  W = gwv; }
    else              { A = gao; W = gwo; }

    float acc[4][4][4];
#pragma unroll
    for (int mt = 0; mt < 4; mt++)
#pragma unroll
        for (int nt = 0; nt < 4; nt++)
#pragma unroll
            for (int f = 0; f < 4; f++) acc[mt][nt][f] = 0.0f;

    const uint32_t a_frag = (wm + (lane & 15)) * 80 + (lane >> 4) * 16;
    const uint32_t b_frag = (lane & 15) * 272 + wn * 2 + (lane >> 4) * 16;

    auto issue = [&](int s) {
        const int k0 = s * 32;
        const uint32_t st = sb + (s & 3) * ST_STRIDE;
#pragma unroll
        for (int i = 0; i < 2; i++) {     // A: 512 16B-chunks
            int c = tid + i * 256;
            int row = c >> 2, cc = c & 3;
            size_t g = (size_t)(m0 + row) * 2048 + k0 + cc * 8;
            cp16(st + row * 80 + cc * 16, A + g);
        }
#pragma unroll
        for (int i = 0; i < 2; i++) {     // W: 512 16B-chunks
            int c = tid + i * 256;
            int row = c >> 4, cc = c & 15;
            size_t g = (size_t)(k0 + row) * 2048 + n0 + cc * 8;
            cp16(st + ST_W + row * 272 + cc * 16, W + g);
        }
    };

    issue(0); cp_commit();
    issue(1); cp_commit();
    issue(2); cp_commit();

    const int NS = 64;
    for (int s = 0; s < NS; s++) {
        cp_wait<2>();
        __syncthreads();
        if (s + 3 < NS) issue(s + 3);
        cp_commit();

        const uint32_t base = sb + (s & 3) * ST_STRIDE;
        const uint32_t ab = base;
        const uint32_t wb = base + ST_W;

#pragma unroll
        for (int ks = 0; ks < 2; ks++) {
            uint32_t ah[4][4];
#pragma unroll
            for (int mt = 0; mt < 4; mt++)
                ldsm_x4(ah[mt], ab + a_frag + mt * 1280 + ks * 32);
            uint32_t bh[2][4];
#pragma unroll
            for (int np = 0; np < 2; np++)
                ldsm_x4_t(bh[np], wb + b_frag + ks * 4352 + np * 32);
#pragma unroll
            for (int mt = 0; mt < 4; mt++)
#pragma unroll
                for (int nt = 0; nt < 4; nt++)
                    mma_f16(acc[mt][nt], ah[mt], &bh[nt >> 1][(nt & 1) * 2]);
        }
    }

    // ---- epilogue ----
    const int lrow = lane >> 2;
    const int lcol = (lane & 3) * 2;
    const int h = blockIdx.x;
    const float QS = 0.0883883476483184405f * 1.4426950408889634f;

#pragma unroll
    for (int mt = 0; mt < 4; mt++) {
#pragma unroll
        for (int rh = 0; rh < 2; rh++) {
            const int m = m0 + wm + mt * 16 + lrow + rh * 8;
            if (OP == 3) {
                float* dst = Cout + (size_t)m * ND_ + n0;
#pragma unroll
                for (int nt = 0; nt < 4; nt++) {
                    int d = wn + nt * 8 + lcol;
                    *(float2*)(dst + d) = make_float2(acc[mt][nt][rh * 2 + 0],
                                                      acc[mt][nt][rh * 2 + 1]);
                }
            } else {
                const int b = m >> 11;
                const int t = m & (T_ - 1);
                const size_t rowoff = (((size_t)(b * H_ + h) * T_ + t) << 7);
                if (OP == 2) {
#pragma unroll
                    for (int nt = 0; nt < 4; nt++) {
                        int d = wn + nt * 8 + lcol;
                        uint32_t hh, ll;
                        cvt_hilo2_f16(acc[mt][nt][rh * 2 + 0], acc[mt][nt][rh * 2 + 1], hh, ll);
                        *(uint32_t*)(gv_hi + rowoff + d) = hh;
                        *(uint32_t*)(gv_lo + rowoff + d) = ll;
                    }
                } else {
#pragma unroll
                    for (int nt = 0; nt < 4; nt++) {
                        int d = wn + nt * 8 + lcol;
                        float x0 = acc[mt][nt][rh * 2 + 0];
                        float x1 = acc[mt][nt][rh * 2 + 1];
                        float cs = g_cos[t * 64 + (d >> 1)];
                        float sn = g_sin[t * 64 + (d >> 1)];
                        float r0 = x0 * cs - x1 * sn;
                        float r1 = x0 * sn + x1 * cs;
                        if (OP == 0) {
                            *(uint32_t*)(gq + rowoff + d) = pack_f16x2(r0 * QS, r1 * QS);
                        } else {
                            uint32_t hh, ll;
                            cvt_hilo2_f16(r0, r1, hh, ll);
                            *(uint32_t*)(gk_hi + rowoff + d) = hh;
                            *(uint32_t*)(gk_lo + rowoff + d) = ll;
                        }
                    }
                }
            }
        }
    }
}

// ---------------------------------------------------------------------------
// Tensor-core flash attention: fp16x2 S (Q single fp16, K hi/lo), fp16x2 PV.
// Heavy-first q-tile remap; warp-level skip of fully-masked tiles;
// one __syncthreads per kv-tile. (Unchanged from R14.)
// ---------------------------------------------------------------------------
#define KV_OFF 34816
#define KV_STRIDE 69632
#define KV_KLO 17408
#define KV_VHI 34816
#define KV_VLO 52224
#define ATT_SMEM (KV_OFF + 2 * KV_STRIDE)   // 174080

__global__ void __launch_bounds__(256, 1) attn_mma_kernel() {
    extern __shared__ char smc[];
    const uint32_t sb = smem_u32(smc);
    const int tid  = threadIdx.x;
    const int lane = tid & 31;
    const int wid  = tid >> 5;
    const int bh   = blockIdx.y;
    const int b    = bh >> 4;
    const int h    = bh & (H_ - 1);
    const int qt   = (int)(gridDim.x - 1) - blockIdx.x;   // heavy tiles first
    const int q0   = qt * 128;
    const int wm   = wid * 16;
    const int lrow = lane >> 2;
    const int lcol2 = (lane & 3) * 2;

    const __half* qg  = gq    + (size_t)bh * T_ * D_;
    const __half* khi = gk_hi + (size_t)bh * T_ * D_;
    const __half* klo = gk_lo + (size_t)bh * T_ * D_;
    const __half* vhi = gv_hi + (size_t)bh * T_ * D_;
    const __half* vlo = gv_lo + (size_t)bh * T_ * D_;

#pragma unroll
    for (int i = 0; i < 8; i++) {
        int c = tid + i * 256;
        int row = c >> 4, cc = c & 15;
        size_t g = (size_t)(q0 + row) * 128 + cc * 8;
        cp16(sb + row * 272 + cc * 16, qg + g);
    }
    cp_commit();

    auto issue_kv = [&](int buf, int k0) {
        uint32_t base = sb + KV_OFF + buf * KV_STRIDE;
#pragma unroll
        for (int i = 0; i < 4; i++) {
            int c = tid + i * 256;
            int row = c >> 4, cc = c & 15;
            size_t g = (size_t)(k0 + row) * 128 + cc * 8;
            uint32_t d = base + row * 272 + cc * 16;
            cp16(d, khi + g);
            cp16(d + KV_KLO, klo + g);
            cp16(d + KV_VHI, vhi + g);
            cp16(d + KV_VLO, vlo + g);
        }
    };

    issue_kv(0, 0);
    cp_commit();

    const uint32_t aq_frag = (wm + (lane & 15)) * 272 + (lane >> 4) * 16;
    const int kb_row = (lane & 7) + ((lane >> 4) << 3);
    const uint32_t kb_frag = kb_row * 272 + ((lane >> 3) & 1) * 16;
    const uint32_t vb_frag = (lane & 15) * 272 + (lane >> 4) * 16;

    float o[16][4];
#pragma unroll
    for (int dt = 0; dt < 16; dt++)
#pragma unroll
        for (int f = 0; f < 4; f++) o[dt][f] = 0.0f;
    float m0 = -1e30f, m1 = -1e30f, l0 = 0.0f, l1 = 0.0f;

    const int njt = 2 * qt + 2;

    for (int jt = 0; jt < njt; jt++) {
        cp_wait<0>();
        __syncthreads();
        if (jt + 1 < njt) issue_kv((jt + 1) & 1, (jt + 1) * 64);
        cp_commit();

        const int k0 = jt * 64;
        if (k0 <= q0 + wm + 15) {
            const uint32_t kvb = sb + KV_OFF + (jt & 1) * KV_STRIDE;
            const uint32_t aqh = sb + aq_frag;
            const uint32_t kbh = kvb + kb_frag;
            const uint32_t vbh = kvb + KV_VHI + vb_frag;

            float s[8][4];
#pragma unroll
            for (int nt = 0; nt < 8; nt++)
#pragma unroll
                for (int f = 0; f < 4; f++) s[nt][f] = 0.0f;

#pragma unroll
            for (int ks = 0; ks < 8; ks++) {
                uint32_t ah[4];
                ldsm_x4(ah, aqh + ks * 32);
                uint32_t kh[4][4], kl[4][4];
#pragma unroll
                for (int np = 0; np < 4; np++) {
                    uint32_t off = np * 4352 + ks * 32;
                    ldsm_x4(kh[np], kbh + off);
                    ldsm_x4(kl[np], kbh + KV_KLO + off);
                }
#pragma unroll
                for (int np = 0; np < 4; np++) {
                    mma_f16(s[2 * np],     ah, kh[np]);
                    mma_f16(s[2 * np + 1], ah, kh[np] + 2);
                }
#pragma unroll
                for (int np = 0; np < 4; np++) {
                    mma_f16(s[2 * np],     ah, kl[np]);
                    mma_f16(s[2 * np + 1], ah, kl[np] + 2);
                }
            }

            if (k0 + 63 > q0 + wm) {
                const int row0 = q0 + wm + lrow;
                const int row1 = row0 + 8;
#pragma unroll
                for (int nt = 0; nt < 8; nt++) {
                    int c0 = k0 + nt * 8 + lcol2;
                    if (c0 > row0)     s[nt][0] = -1e30f;
                    if (c0 + 1 > row0) s[nt][1] = -1e30f;
                    if (c0 > row1)     s[nt][2] = -1e30f;
                    if (c0 + 1 > row1) s[nt][3] = -1e30f;
                }
            }

            float mx0 = -1e30f, mx1 = -1e30f;
#pragma unroll
            for (int nt = 0; nt < 8; nt++) {
                mx0 = fmaxf(mx0, fmaxf(s[nt][0], s[nt][1]));
                mx1 = fmaxf(mx1, fmaxf(s[nt][2], s[nt][3]));
            }
            mx0 = fmaxf(mx0, __shfl_xor_sync(0xffffffffu, mx0, 1));
            mx0 = fmaxf(mx0, __shfl_xor_sync(0xffffffffu, mx0, 2));
            mx1 = fmaxf(mx1, __shfl_xor_sync(0xffffffffu, mx1, 1));
            mx1 = fmaxf(mx1, __shfl_xor_sync(0xffffffffu, mx1, 2));
            float m0n = fmaxf(m0, mx0);
            float m1n = fmaxf(m1, mx1);
            float corr0 = exp2p(m0 - m0n);
            float corr1 = exp2p(m1 - m1n);
            m0 = m0n; m1 = m1n;

            uint32_t ph01[8], ph23[8];
            float sum0 = 0.0f, sum1 = 0.0f;
#pragma unroll
            for (int nt = 0; nt < 8; nt++) {
                float p0 = exp2p(s[nt][0] - m0);
                float p1 = exp2p(s[nt][1] - m0);
                float p2 = exp2p(s[nt][2] - m1);
                float p3 = exp2p(s[nt][3] - m1);
                sum0 += p0 + p1;
                sum1 += p2 + p3;
                ph01[nt] = pack_f16x2(p0, p1);
                ph23[nt] = pack_f16x2(p2, p3);
            }
            sum0 += __shfl_xor_sync(0xffffffffu, sum0, 1);
            sum0 += __shfl_xor_sync(0xffffffffu, sum0, 2);
            sum1 += __shfl_xor_sync(0xffffffffu, sum1, 1);
            sum1 += __shfl_xor_sync(0xffffffffu, sum1, 2);
            l0 = l0 * corr0 + sum0;
            l1 = l1 * corr1 + sum1;

#pragma unroll
            for (int dt = 0; dt < 16; dt++) {
                o[dt][0] *= corr0; o[dt][1] *= corr0;
                o[dt][2] *= corr1; o[dt][3] *= corr1;
            }

#pragma unroll
            for (int ks = 0; ks < 4; ks++) {
                uint32_t aph[4] = { ph01[2 * ks], ph23[2 * ks],
                                    ph01[2 * ks + 1], ph23[2 * ks + 1] };
#pragma unroll
                for (int half = 0; half < 2; half++) {
                    uint32_t vh[4][4], vl[4][4];
#pragma unroll
                    for (int j = 0; j < 4; j++) {
                        int np = half * 4 + j;
                        uint32_t off = ks * 4352 + np * 32;
                        ldsm_x4_t(vh[j], vbh + off);
                        ldsm_x4_t(vl[j], vbh + (KV_VLO - KV_VHI) + off);
                    }
#pragma unroll
                    for (int j = 0; j < 4; j++) {
                        int np = half * 4 + j;
                        mma_f16(o[2 * np],     aph, vh[j]);
                        mma_f16(o[2 * np + 1], aph, vh[j] + 2);
                    }
#pragma unroll
                    for (int j = 0; j < 4; j++) {
                        int np = half * 4 + j;
                        mma_f16(o[2 * np],     aph, vl[j]);
                        mma_f16(o[2 * np + 1], aph, vl[j] + 2);
                    }
                }
            }
        }
    }

    // ---- epilogue: normalize, store gao as single fp16 ----
    const float inv0 = 1.0f / l0;
    const float inv1 = 1.0f / l1;
    const int row0 = q0 + wm + lrow;
    const int row1 = row0 + 8;
    const size_t o0 = (size_t)(b * T_ + row0) * C_ + h * D_;
    const size_t o1 = (size_t)(b * T_ + row1) * C_ + h * D_;
#pragma unroll
    for (int dt = 0; dt < 16; dt++) {
        int d = dt * 8 + lcol2;
        *(uint32_t*)(gao + o0 + d) = pack_f16x2(o[dt][0] * inv0, o[dt][1] * inv0);
        *(uint32_t*)(gao + o1 + d) = pack_f16x2(o[dt][2] * inv1, o[dt][3] * inv1);
    }
}

// ---------------------------------------------------------------------------
// Launch
// ---------------------------------------------------------------------------
extern "C" void kernel_launch(void* const* d_in, const int* in_sizes, int n_in,
                              void* d_out, int out_size) {
    const float* x  = (const float*)d_in[0];
    const float* wq = (const float*)d_in[2];
    const float* wk = (const float*)d_in[3];
    const float* wv = (const float*)d_in[4];
    const float* wo = (const float*)d_in[5];
    float* out = (float*)d_out;

    rope_table_kernel<<<(T_ * (D_ / 2) + 255) / 256, 256>>>();

    const size_t total = NX_ + 4 * NW_;
    split_all_kernel<<<(unsigned)(total / 1024), 256>>>(x, wq, wk, wv, wo);

    cudaFuncSetAttribute(gemm_mma_kernel<0>, cudaFuncAttributeMaxDynamicSharedMemorySize, GEMM_SMEM);
    cudaFuncSetAttribute(gemm_mma_kernel<1>, cudaFuncAttributeMaxDynamicSharedMemorySize, GEMM_SMEM);
    cudaFuncSetAttribute(gemm_mma_kernel<2>, cudaFuncAttributeMaxDynamicSharedMemorySize, GEMM_SMEM);
    cudaFuncSetAttribute(gemm_mma_kernel<3>, cudaFuncAttributeMaxDynamicSharedMemorySize, GEMM_SMEM);
    cudaFuncSetAttribute(attn_mma_kernel,    cudaFuncAttributeMaxDynamicSharedMemorySize, ATT_SMEM);

    dim3 gg(ND_ / 128, M_ / 128);  // (16, 32)
    gemm_mma_kernel<0><<<gg, 256, GEMM_SMEM>>>(nullptr);
    gemm_mma_kernel<1><<<gg, 256, GEMM_SMEM>>>(nullptr);
    gemm_mma_kernel<2><<<gg, 256, GEMM_SMEM>>>(nullptr);

    attn_mma_kernel<<<dim3(T_ / 128, B_ * H_), 256, ATT_SMEM>>>();

    gemm_mma_kernel<3><<<gg, 256, GEMM_SMEM>>>(out);
}

// round 16
// speedup vs baseline: 2.3217x; 1.1598x over previous
#include <cuda_runtime.h>
#include <cuda_bf16.h>
#include <cuda_fp16.h>
#include <math.h>
#include <stdint.h>

// Problem constants
#define B_ 2
#define T_ 2048
#define C_ 2048
#define H_ 16
#define D_ 128
#define M_ (B_ * T_)
#define ND_ (H_ * D_)
#define NX_ ((size_t)M_ * C_)
#define NW_ ((size_t)C_ * ND_)

// ---------------------------------------------------------------------------
// Scratch. GEMM: A, W single fp16. Attention: Q,K single fp16 (QS folded in Q),
// V fp16 hi/lo (2-term PV), gao single fp16.
// ---------------------------------------------------------------------------
__device__ __half gx[NX_];
__device__ __half gwq[NW_], gwk[NW_], gwv[NW_], gwo[NW_];
__device__ __half gq[(size_t)B_ * H_ * T_ * D_];
__device__ __half gk[(size_t)B_ * H_ * T_ * D_];
__device__ __half gv_hi[(size_t)B_ * H_ * T_ * D_], gv_lo[(size_t)B_ * H_ * T_ * D_];
__device__ __half gao[NX_];
__device__ float g_cos[T_ * (D_ / 2)];
__device__ float g_sin[T_ * (D_ / 2)];

// ---------------------------------------------------------------------------
// Helpers
// ---------------------------------------------------------------------------
__device__ __forceinline__ uint32_t smem_u32(const void* p) {
    uint32_t a;
    asm("{ .reg .u64 t; cvta.to.shared.u64 t, %1; cvt.u32.u64 %0, t; }" : "=r"(a) : "l"(p));
    return a;
}
__device__ __forceinline__ void ldsm_x4(uint32_t* r, uint32_t addr) {
    asm volatile("ldmatrix.sync.aligned.m8n8.x4.shared.b16 {%0,%1,%2,%3}, [%4];"
                 : "=r"(r[0]), "=r"(r[1]), "=r"(r[2]), "=r"(r[3]) : "r"(addr));
}
__device__ __forceinline__ void ldsm_x4_t(uint32_t* r, uint32_t addr) {
    asm volatile("ldmatrix.sync.aligned.m8n8.x4.trans.shared.b16 {%0,%1,%2,%3}, [%4];"
                 : "=r"(r[0]), "=r"(r[1]), "=r"(r[2]), "=r"(r[3]) : "r"(addr));
}
__device__ __forceinline__ void mma_f16(float* c, const uint32_t* a, const uint32_t* b) {
    asm volatile("mma.sync.aligned.m16n8k16.row.col.f32.f16.f16.f32 "
                 "{%0,%1,%2,%3}, {%4,%5,%6,%7}, {%8,%9}, {%0,%1,%2,%3};"
                 : "+f"(c[0]), "+f"(c[1]), "+f"(c[2]), "+f"(c[3])
                 : "r"(a[0]), "r"(a[1]), "r"(a[2]), "r"(a[3]), "r"(b[0]), "r"(b[1]));
}
__device__ __forceinline__ void cvt_hilo2_f16(float x, float y, uint32_t& hi, uint32_t& lo) {
    __half hx = __float2half(x);
    __half hy = __float2half(y);
    __half lx = __float2half(x - __half2float(hx));
    __half ly = __float2half(y - __half2float(hy));
    hi = ((uint32_t)__half_as_ushort(hy) << 16) | __half_as_ushort(hx);
    lo = ((uint32_t)__half_as_ushort(ly) << 16) | __half_as_ushort(lx);
}
__device__ __forceinline__ uint32_t pack_f16x2(float lo, float hi) {
    uint32_t r;
    asm("cvt.rn.f16x2.f32 %0, %1, %2;" : "=r"(r) : "f"(hi), "f"(lo));
    return r;
}
__device__ __forceinline__ void cp16(uint32_t dst, const void* src) {
    asm volatile("cp.async.cg.shared.global [%0], [%1], 16;" :: "r"(dst), "l"(src));
}
__device__ __forceinline__ void cp_commit() {
    asm volatile("cp.async.commit_group;" ::: "memory");
}
template <int N>
__device__ __forceinline__ void cp_wait() {
    asm volatile("cp.async.wait_group %0;" :: "n"(N) : "memory");
}
// exp2 on the FMA pipe
__device__ __forceinline__ float exp2p(float t) {
    t = fmaxf(t, -100.0f);
    float nf = rintf(t);
    float f = t - nf;
    float p =             1.3333558146e-3f;
    p = fmaf(p, f, 9.6181291076e-3f);
    p = fmaf(p, f, 5.5504108665e-2f);
    p = fmaf(p, f, 2.4022650696e-1f);
    p = fmaf(p, f, 6.9314718056e-1f);
    p = fmaf(p, f, 1.0f);
    float sc = __int_as_float(((int)nf + 127) << 23);
    return p * sc;
}

// ---------------------------------------------------------------------------
// RoPE table + one-time input conversion: x, weights -> single fp16
// ---------------------------------------------------------------------------
__global__ void rope_table_kernel() {
    int i = blockIdx.x * blockDim.x + threadIdx.x;
    if (i >= T_ * (D_ / 2)) return;
    int t  = i >> 6;
    int d2 = i & 63;
    float inv = powf(10000.0f, -((float)(2 * d2)) / (float)D_);
    float ang = (float)t * inv;
    g_cos[i] = cosf(ang);
    g_sin[i] = sinf(ang);
}

__global__ void split_all_kernel(const float* __restrict__ x,
                                 const float* __restrict__ wq,
                                 const float* __restrict__ wk,
                                 const float* __restrict__ wv,
                                 const float* __restrict__ wo) {
    size_t idx = ((size_t)blockIdx.x * blockDim.x + threadIdx.x) * 4;
    const float* src;
    __half* dst;
    size_t base;
    if (idx < NX_) {
        src = x; dst = gx; base = idx;
    } else {
        size_t w = idx - NX_;
        int which = (int)(w >> 22);       // NW_ = 2^22
        base = w & (NW_ - 1);
        switch (which) {
            case 0:  src = wq; dst = gwq; break;
            case 1:  src = wk; dst = gwk; break;
            case 2:  src = wv; dst = gwv; break;
            default: src = wo; dst = gwo; break;
        }
    }
    float4 v = *(const float4*)(src + base);
    *(uint2*)(dst + base) = make_uint2(pack_f16x2(v.x, v.y), pack_f16x2(v.z, v.w));
}

// ---------------------------------------------------------------------------
// 1-term fp16 GEMM, BK=64 (32 K-stages, half the barriers of BK=32),
// 3-stage cp.async (wait_group<1>), one __syncthreads per stage, 2 CTAs/SM.
// CTA tile 128x128, warp 64x32.
// A: 128 rows * 144 B (128 data + 16 pad). W: 64 rows * 272 B.
// ---------------------------------------------------------------------------
#define ST_W 18432                   // A bytes per stage
#define ST_STRIDE 35840              // + W 64*272 = 17408
#define GEMM_SMEM (3 * ST_STRIDE)    // 107520; x2 CTAs = 215040 <= 228KB

// Shared GEMM body; OPZ: 0/1/2 = Q/K/V (z-dispatch), 3 = out-proj.
template <int FUSED>
__device__ __forceinline__ void gemm_body(int opz, float* __restrict__ Cout) {
    extern __shared__ char smem[];
    const uint32_t sb = smem_u32(smem);
    const int tid  = threadIdx.x;
    const int lane = tid & 31;
    const int wid  = tid >> 5;
    const int m0 = blockIdx.y * 128;
    const int n0 = blockIdx.x * 128;
    const int wm = (wid & 1) * 64;
    const int wn = (wid >> 1) * 32;

    const __half *A, *W;
    if (FUSED) {
        A = gx;
        W = (opz == 0) ? gwq : (opz == 1) ? gwk : gwv;
    } else {
        A = gao; W = gwo;
    }

    float acc[4][4][4];
#pragma unroll
    for (int mt = 0; mt < 4; mt++)
#pragma unroll
        for (int nt = 0; nt < 4; nt++)
#pragma unroll
            for (int f = 0; f < 4; f++) acc[mt][nt][f] = 0.0f;

    const uint32_t a_frag = (wm + (lane & 15)) * 144 + (lane >> 4) * 16;
    const uint32_t b_frag = (lane & 15) * 272 + wn * 2 + (lane >> 4) * 16;

    auto issue = [&](int s) {
        const int k0 = s * 64;
        const uint32_t st = sb + (s % 3) * ST_STRIDE;
#pragma unroll
        for (int i = 0; i < 4; i++) {     // A: 1024 16B-chunks (128 rows x 8)
            int c = tid + i * 256;
            int row = c >> 3, cc = c & 7;
            size_t g = (size_t)(m0 + row) * 2048 + k0 + cc * 8;
            cp16(st + row * 144 + cc * 16, A + g);
        }
#pragma unroll
        for (int i = 0; i < 4; i++) {     // W: 1024 16B-chunks (64 rows x 16)
            int c = tid + i * 256;
            int row = c >> 4, cc = c & 15;
            size_t g = (size_t)(k0 + row) * 2048 + n0 + cc * 8;
            cp16(st + ST_W + row * 272 + cc * 16, W + g);
        }
    };

    issue(0); cp_commit();
    issue(1); cp_commit();

    const int NS = 32;
    for (int s = 0; s < NS; s++) {
        cp_wait<1>();
        __syncthreads();
        if (s + 2 < NS) issue(s + 2);
        cp_commit();

        const uint32_t base = sb + (s % 3) * ST_STRIDE;
        const uint32_t ab = base;
        const uint32_t wb = base + ST_W;

#pragma unroll
        for (int ks = 0; ks < 4; ks++) {
            uint32_t ah[4][4];
#pragma unroll
            for (int mt = 0; mt < 4; mt++)
                ldsm_x4(ah[mt], ab + a_frag + mt * 2304 + ks * 32);
            uint32_t bh[2][4];
#pragma unroll
            for (int np = 0; np < 2; np++)
                ldsm_x4_t(bh[np], wb + b_frag + ks * 4352 + np * 32);
#pragma unroll
            for (int mt = 0; mt < 4; mt++)
#pragma unroll
                for (int nt = 0; nt < 4; nt++)
                    mma_f16(acc[mt][nt], ah[mt], &bh[nt >> 1][(nt & 1) * 2]);
        }
    }

    // ---- epilogue ----
    const int lrow = lane >> 2;
    const int lcol = (lane & 3) * 2;
    const int h = blockIdx.x;
    const float QS = 0.0883883476483184405f * 1.4426950408889634f;

#pragma unroll
    for (int mt = 0; mt < 4; mt++) {
#pragma unroll
        for (int rh = 0; rh < 2; rh++) {
            const int m = m0 + wm + mt * 16 + lrow + rh * 8;
            if (!FUSED) {
                float* dst = Cout + (size_t)m * ND_ + n0;
#pragma unroll
                for (int nt = 0; nt < 4; nt++) {
                    int d = wn + nt * 8 + lcol;
                    *(float2*)(dst + d) = make_float2(acc[mt][nt][rh * 2 + 0],
                                                      acc[mt][nt][rh * 2 + 1]);
                }
            } else {
                const int b = m >> 11;
                const int t = m & (T_ - 1);
                const size_t rowoff = (((size_t)(b * H_ + h) * T_ + t) << 7);
                if (opz == 2) {
#pragma unroll
                    for (int nt = 0; nt < 4; nt++) {
                        int d = wn + nt * 8 + lcol;
                        uint32_t hh, ll;
                        cvt_hilo2_f16(acc[mt][nt][rh * 2 + 0], acc[mt][nt][rh * 2 + 1], hh, ll);
                        *(uint32_t*)(gv_hi + rowoff + d) = hh;
                        *(uint32_t*)(gv_lo + rowoff + d) = ll;
                    }
                } else {
#pragma unroll
                    for (int nt = 0; nt < 4; nt++) {
                        int d = wn + nt * 8 + lcol;
                        float x0 = acc[mt][nt][rh * 2 + 0];
                        float x1 = acc[mt][nt][rh * 2 + 1];
                        float cs = g_cos[t * 64 + (d >> 1)];
                        float sn = g_sin[t * 64 + (d >> 1)];
                        float r0 = x0 * cs - x1 * sn;
                        float r1 = x0 * sn + x1 * cs;
                        if (opz == 0) {
                            *(uint32_t*)(gq + rowoff + d) = pack_f16x2(r0 * QS, r1 * QS);
                        } else {
                            *(uint32_t*)(gk + rowoff + d) = pack_f16x2(r0, r1);
                        }
                    }
                }
            }
        }
    }
}

__global__ void __launch_bounds__(256, 2) gemm_qkv_kernel() {
    gemm_body<1>((int)blockIdx.z, nullptr);
}
__global__ void __launch_bounds__(256, 2) gemm_o_kernel(float* __restrict__ Cout) {
    gemm_body<0>(3, Cout);
}

// ---------------------------------------------------------------------------
// Tensor-core flash attention: 1-term fp16 S (Q, K single fp16),
// fp16x2 PV (V hi/lo). Heavy-first q-tile remap; warp-level masked-tile skip;
// one __syncthreads per kv-tile.
// ---------------------------------------------------------------------------
#define KV_OFF 34816                 // Q: 128 * 272
#define KV_STRIDE 52224              // K + Vhi + Vlo, each 64*272=17408
#define KV_VHI 17408
#define KV_VLO 34816
#define ATT_SMEM (KV_OFF + 2 * KV_STRIDE)   // 139264

__global__ void __launch_bounds__(256, 1) attn_mma_kernel() {
    extern __shared__ char smc[];
    const uint32_t sb = smem_u32(smc);
    const int tid  = threadIdx.x;
    const int lane = tid & 31;
    const int wid  = tid >> 5;
    const int bh   = blockIdx.y;
    const int b    = bh >> 4;
    const int h    = bh & (H_ - 1);
    const int qt   = (int)(gridDim.x - 1) - blockIdx.x;   // heavy tiles first
    const int q0   = qt * 128;
    const int wm   = wid * 16;
    const int lrow = lane >> 2;
    const int lcol2 = (lane & 3) * 2;

    const __half* qg  = gq    + (size_t)bh * T_ * D_;
    const __half* kg  = gk    + (size_t)bh * T_ * D_;
    const __half* vhi = gv_hi + (size_t)bh * T_ * D_;
    const __half* vlo = gv_lo + (size_t)bh * T_ * D_;

#pragma unroll
    for (int i = 0; i < 8; i++) {
        int c = tid + i * 256;
        int row = c >> 4, cc = c & 15;
        size_t g = (size_t)(q0 + row) * 128 + cc * 8;
        cp16(sb + row * 272 + cc * 16, qg + g);
    }
    cp_commit();

    auto issue_kv = [&](int buf, int k0) {
        uint32_t base = sb + KV_OFF + buf * KV_STRIDE;
#pragma unroll
        for (int i = 0; i < 4; i++) {
            int c = tid + i * 256;
            int row = c >> 4, cc = c & 15;
            size_t g = (size_t)(k0 + row) * 128 + cc * 8;
            uint32_t d = base + row * 272 + cc * 16;
            cp16(d, kg + g);
            cp16(d + KV_VHI, vhi + g);
            cp16(d + KV_VLO, vlo + g);
        }
    };

    issue_kv(0, 0);
    cp_commit();

    const uint32_t aq_frag = (wm + (lane & 15)) * 272 + (lane >> 4) * 16;
    const int kb_row = (lane & 7) + ((lane >> 4) << 3);
    const uint32_t kb_frag = kb_row * 272 + ((lane >> 3) & 1) * 16;
    const uint32_t vb_frag = (lane & 15) * 272 + (lane >> 4) * 16;

    float o[16][4];
#pragma unroll
    for (int dt = 0; dt < 16; dt++)
#pragma unroll
        for (int f = 0; f < 4; f++) o[dt][f] = 0.0f;
    float m0 = -1e30f, m1 = -1e30f, l0 = 0.0f, l1 = 0.0f;

    const int njt = 2 * qt + 2;

    for (int jt = 0; jt < njt; jt++) {
        cp_wait<0>();
        __syncthreads();
        if (jt + 1 < njt) issue_kv((jt + 1) & 1, (jt + 1) * 64);
        cp_commit();

        const int k0 = jt * 64;
        if (k0 <= q0 + wm + 15) {
            const uint32_t kvb = sb + KV_OFF + (jt & 1) * KV_STRIDE;
            const uint32_t aqh = sb + aq_frag;
            const uint32_t kbh = kvb + kb_frag;
            const uint32_t vbh = kvb + KV_VHI + vb_frag;

            // ---- S = Q K^T (1-term fp16) ----
            float s[8][4];
#pragma unroll
            for (int nt = 0; nt < 8; nt++)
#pragma unroll
                for (int f = 0; f < 4; f++) s[nt][f] = 0.0f;

#pragma unroll
            for (int ks = 0; ks < 8; ks++) {
                uint32_t ah[4];
                ldsm_x4(ah, aqh + ks * 32);
                uint32_t kh[4][4];
#pragma unroll
                for (int np = 0; np < 4; np++)
                    ldsm_x4(kh[np], kbh + np * 4352 + ks * 32);
#pragma unroll
                for (int np = 0; np < 4; np++) {
                    mma_f16(s[2 * np],     ah, kh[np]);
                    mma_f16(s[2 * np + 1], ah, kh[np] + 2);
                }
            }

            if (k0 + 63 > q0 + wm) {
                const int row0 = q0 + wm + lrow;
                const int row1 = row0 + 8;
#pragma unroll
                for (int nt = 0; nt < 8; nt++) {
                    int c0 = k0 + nt * 8 + lcol2;
                    if (c0 > row0)     s[nt][0] = -1e30f;
                    if (c0 + 1 > row0) s[nt][1] = -1e30f;
                    if (c0 > row1)     s[nt][2] = -1e30f;
                    if (c0 + 1 > row1) s[nt][3] = -1e30f;
                }
            }

            float mx0 = -1e30f, mx1 = -1e30f;
#pragma unroll
            for (int nt = 0; nt < 8; nt++) {
                mx0 = fmaxf(mx0, fmaxf(s[nt][0], s[nt][1]));
                mx1 = fmaxf(mx1, fmaxf(s[nt][2], s[nt][3]));
            }
            mx0 = fmaxf(mx0, __shfl_xor_sync(0xffffffffu, mx0, 1));
            mx0 = fmaxf(mx0, __shfl_xor_sync(0xffffffffu, mx0, 2));
            mx1 = fmaxf(mx1, __shfl_xor_sync(0xffffffffu, mx1, 1));
            mx1 = fmaxf(mx1, __shfl_xor_sync(0xffffffffu, mx1, 2));
            float m0n = fmaxf(m0, mx0);
            float m1n = fmaxf(m1, mx1);
            float corr0 = exp2p(m0 - m0n);
            float corr1 = exp2p(m1 - m1n);
            m0 = m0n; m1 = m1n;

            uint32_t ph01[8], ph23[8];
            float sum0 = 0.0f, sum1 = 0.0f;
#pragma unroll
            for (int nt = 0; nt < 8; nt++) {
                float p0 = exp2p(s[nt][0] - m0);
                float p1 = exp2p(s[nt][1] - m0);
                float p2 = exp2p(s[nt][2] - m1);
                float p3 = exp2p(s[nt][3] - m1);
                sum0 += p0 + p1;
                sum1 += p2 + p3;
                ph01[nt] = pack_f16x2(p0, p1);
                ph23[nt] = pack_f16x2(p2, p3);
            }
            sum0 += __shfl_xor_sync(0xffffffffu, sum0, 1);
            sum0 += __shfl_xor_sync(0xffffffffu, sum0, 2);
            sum1 += __shfl_xor_sync(0xffffffffu, sum1, 1);
            sum1 += __shfl_xor_sync(0xffffffffu, sum1, 2);
            l0 = l0 * corr0 + sum0;
            l1 = l1 * corr1 + sum1;

#pragma unroll
            for (int dt = 0; dt < 16; dt++) {
                o[dt][0] *= corr0; o[dt][1] *= corr0;
                o[dt][2] *= corr1; o[dt][3] *= corr1;
            }

            // ---- O += P V (fp16x2: P*(Vhi + Vlo)) ----
#pragma unroll
            for (int ks = 0; ks < 4; ks++) {
                uint32_t aph[4] = { ph01[2 * ks], ph23[2 * ks],
                                    ph01[2 * ks + 1], ph23[2 * ks + 1] };
#pragma unroll
                for (int half = 0; half < 2; half++) {
                    uint32_t vh[4][4], vl[4][4];
#pragma unroll
                    for (int j = 0; j < 4; j++) {
                        int np = half * 4 + j;
                        uint32_t off = ks * 4352 + np * 32;
                        ldsm_x4_t(vh[j], vbh + off);
                        ldsm_x4_t(vl[j], vbh + (KV_VLO - KV_VHI) + off);
                    }
#pragma unroll
                    for (int j = 0; j < 4; j++) {
                        int np = half * 4 + j;
                        mma_f16(o[2 * np],     aph, vh[j]);
                        mma_f16(o[2 * np + 1], aph, vh[j] + 2);
                    }
#pragma unroll
                    for (int j = 0; j < 4; j++) {
                        int np = half * 4 + j;
                        mma_f16(o[2 * np],     aph, vl[j]);
                        mma_f16(o[2 * np + 1], aph, vl[j] + 2);
                    }
                }
            }
        }
    }

    // ---- epilogue: normalize, store gao as single fp16 ----
    const float inv0 = 1.0f / l0;
    const float inv1 = 1.0f / l1;
    const int row0 = q0 + wm + lrow;
    const int row1 = row0 + 8;
    const size_t o0 = (size_t)(b * T_ + row0) * C_ + h * D_;
    const size_t o1 = (size_t)(b * T_ + row1) * C_ + h * D_;
#pragma unroll
    for (int dt = 0; dt < 16; dt++) {
        int d = dt * 8 + lcol2;
        *(uint32_t*)(gao + o0 + d) = pack_f16x2(o[dt][0] * inv0, o[dt][1] * inv0);
        *(uint32_t*)(gao + o1 + d) = pack_f16x2(o[dt][2] * inv1, o[dt][3] * inv1);
    }
}

// ---------------------------------------------------------------------------
// Launch
// ---------------------------------------------------------------------------
extern "C" void kernel_launch(void* const* d_in, const int* in_sizes, int n_in,
                              void* d_out, int out_size) {
    const float* x  = (const float*)d_in[0];
    const float* wq = (const float*)d_in[2];
    const float* wk = (const float*)d_in[3];
    const float* wv = (const float*)d_in[4];
    const float* wo = (const float*)d_in[5];
    float* out = (float*)d_out;

    rope_table_kernel<<<(T_ * (D_ / 2) + 255) / 256, 256>>>();

    const size_t total = NX_ + 4 * NW_;
    split_all_kernel<<<(unsigned)(total / 1024), 256>>>(x, wq, wk, wv, wo);

    cudaFuncSetAttribute(gemm_qkv_kernel, cudaFuncAttributeMaxDynamicSharedMemorySize, GEMM_SMEM);
    cudaFuncSetAttribute(gemm_o_kernel,   cudaFuncAttributeMaxDynamicSharedMemorySize, GEMM_SMEM);
    cudaFuncSetAttribute(attn_mma_kernel, cudaFuncAttributeMaxDynamicSharedMemorySize, ATT_SMEM);

    dim3 gqkv(ND_ / 128, M_ / 128, 3);   // (16, 32, 3) = 1536 CTAs in ONE launch
    gemm_qkv_kernel<<<gqkv, 256, GEMM_SMEM>>>();

    attn_mma_kernel<<<dim3(T_ / 128, B_ * H_), 256, ATT_SMEM>>>();

    dim3 go(ND_ / 128, M_ / 128);        // (16, 32)
    gemm_o_kernel<<<go, 256, GEMM_SMEM>>>(out);
}

// round 17
// speedup vs baseline: 2.4322x; 1.0476x over previous
#include <cuda_runtime.h>
#include <cuda_bf16.h>
#include <cuda_fp16.h>
#include <math.h>
#include <stdint.h>

// Problem constants
#define B_ 2
#define T_ 2048
#define C_ 2048
#define H_ 16
#define D_ 128
#define M_ (B_ * T_)
#define ND_ (H_ * D_)
#define NX_ ((size_t)M_ * C_)
#define NW_ ((size_t)C_ * ND_)

// ---------------------------------------------------------------------------
// Scratch. GEMM: A, W single fp16. Attention: Q, K, V single fp16
// (QS folded into Q), gao single fp16.
// ---------------------------------------------------------------------------
__device__ __half gx[NX_];
__device__ __half gwq[NW_], gwk[NW_], gwv[NW_], gwo[NW_];
__device__ __half gq[(size_t)B_ * H_ * T_ * D_];
__device__ __half gk[(size_t)B_ * H_ * T_ * D_];
__device__ __half gv[(size_t)B_ * H_ * T_ * D_];
__device__ __half gao[NX_];
__device__ float g_cos[T_ * (D_ / 2)];
__device__ float g_sin[T_ * (D_ / 2)];

// ---------------------------------------------------------------------------
// Helpers
// ---------------------------------------------------------------------------
__device__ __forceinline__ uint32_t smem_u32(const void* p) {
    uint32_t a;
    asm("{ .reg .u64 t; cvta.to.shared.u64 t, %1; cvt.u32.u64 %0, t; }" : "=r"(a) : "l"(p));
    return a;
}
__device__ __forceinline__ void ldsm_x4(uint32_t* r, uint32_t addr) {
    asm volatile("ldmatrix.sync.aligned.m8n8.x4.shared.b16 {%0,%1,%2,%3}, [%4];"
                 : "=r"(r[0]), "=r"(r[1]), "=r"(r[2]), "=r"(r[3]) : "r"(addr));
}
__device__ __forceinline__ void ldsm_x4_t(uint32_t* r, uint32_t addr) {
    asm volatile("ldmatrix.sync.aligned.m8n8.x4.trans.shared.b16 {%0,%1,%2,%3}, [%4];"
                 : "=r"(r[0]), "=r"(r[1]), "=r"(r[2]), "=r"(r[3]) : "r"(addr));
}
__device__ __forceinline__ void mma_f16(float* c, const uint32_t* a, const uint32_t* b) {
    asm volatile("mma.sync.aligned.m16n8k16.row.col.f32.f16.f16.f32 "
                 "{%0,%1,%2,%3}, {%4,%5,%6,%7}, {%8,%9}, {%0,%1,%2,%3};"
                 : "+f"(c[0]), "+f"(c[1]), "+f"(c[2]), "+f"(c[3])
                 : "r"(a[0]), "r"(a[1]), "r"(a[2]), "r"(a[3]), "r"(b[0]), "r"(b[1]));
}
__device__ __forceinline__ void cvt_hilo2_f16(float x, float y, uint32_t& hi, uint32_t& lo) {
    __half hx = __float2half(x);
    __half hy = __float2half(y);
    __half lx = __float2half(x - __half2float(hx));
    __half ly = __float2half(y - __half2float(hy));
    hi = ((uint32_t)__half_as_ushort(hy) << 16) | __half_as_ushort(hx);
    lo = ((uint32_t)__half_as_ushort(ly) << 16) | __half_as_ushort(lx);
}
__device__ __forceinline__ uint32_t pack_f16x2(float lo, float hi) {
    uint32_t r;
    asm("cvt.rn.f16x2.f32 %0, %1, %2;" : "=r"(r) : "f"(hi), "f"(lo));
    return r;
}
__device__ __forceinline__ void cp16(uint32_t dst, const void* src) {
    asm volatile("cp.async.cg.shared.global [%0], [%1], 16;" :: "r"(dst), "l"(src));
}
__device__ __forceinline__ void cp_commit() {
    asm volatile("cp.async.commit_group;" ::: "memory");
}
template <int N>
__device__ __forceinline__ void cp_wait() {
    asm volatile("cp.async.wait_group %0;" :: "n"(N) : "memory");
}
// exp2 on the FMA pipe
__device__ __forceinline__ float exp2p(float t) {
    t = fmaxf(t, -100.0f);
    float nf = rintf(t);
    float f = t - nf;
    float p =             1.3333558146e-3f;
    p = fmaf(p, f, 9.6181291076e-3f);
    p = fmaf(p, f, 5.5504108665e-2f);
    p = fmaf(p, f, 2.4022650696e-1f);
    p = fmaf(p, f, 6.9314718056e-1f);
    p = fmaf(p, f, 1.0f);
    float sc = __int_as_float(((int)nf + 127) << 23);
    return p * sc;
}

// ---------------------------------------------------------------------------
// RoPE table + one-time input conversion: x, weights -> single fp16
// ---------------------------------------------------------------------------
__global__ void rope_table_kernel() {
    int i = blockIdx.x * blockDim.x + threadIdx.x;
    if (i >= T_ * (D_ / 2)) return;
    int t  = i >> 6;
    int d2 = i & 63;
    float inv = powf(10000.0f, -((float)(2 * d2)) / (float)D_);
    float ang = (float)t * inv;
    g_cos[i] = cosf(ang);
    g_sin[i] = sinf(ang);
}

__global__ void split_all_kernel(const float* __restrict__ x,
                                 const float* __restrict__ wq,
                                 const float* __restrict__ wk,
                                 const float* __restrict__ wv,
                                 const float* __restrict__ wo) {
    size_t idx = ((size_t)blockIdx.x * blockDim.x + threadIdx.x) * 4;
    const float* src;
    __half* dst;
    size_t base;
    if (idx < NX_) {
        src = x; dst = gx; base = idx;
    } else {
        size_t w = idx - NX_;
        int which = (int)(w >> 22);       // NW_ = 2^22
        base = w & (NW_ - 1);
        switch (which) {
            case 0:  src = wq; dst = gwq; break;
            case 1:  src = wk; dst = gwk; break;
            case 2:  src = wv; dst = gwv; break;
            default: src = wo; dst = gwo; break;
        }
    }
    float4 v = *(const float4*)(src + base);
    *(uint2*)(dst + base) = make_uint2(pack_f16x2(v.x, v.y), pack_f16x2(v.z, v.w));
}

// ---------------------------------------------------------------------------
// 1-term fp16 GEMM, BK=64 (32 K-stages), 3-stage cp.async, one sync/stage,
// 2 CTAs/SM. CTA 128x128, warp 64x32. (Unchanged from R16 except V epilogue
// stores single fp16.)
// ---------------------------------------------------------------------------
#define ST_W 18432
#define ST_STRIDE 35840
#define GEMM_SMEM (3 * ST_STRIDE)

template <int FUSED>
__device__ __forceinline__ void gemm_body(int opz, float* __restrict__ Cout) {
    extern __shared__ char smem[];
    const uint32_t sb = smem_u32(smem);
    const int tid  = threadIdx.x;
    const int lane = tid & 31;
    const int wid  = tid >> 5;
    const int m0 = blockIdx.y * 128;
    const int n0 = blockIdx.x * 128;
    const int wm = (wid & 1) * 64;
    const int wn = (wid >> 1) * 32;

    const __half *A, *W;
    if (FUSED) {
        A = gx;
        W = (opz == 0) ? gwq : (opz == 1) ? gwk : gwv;
    } else {
        A = gao; W = gwo;
    }

    float acc[4][4][4];
#pragma unroll
    for (int mt = 0; mt < 4; mt++)
#pragma unroll
        for (int nt = 0; nt < 4; nt++)
#pragma unroll
            for (int f = 0; f < 4; f++) acc[mt][nt][f] = 0.0f;

    const uint32_t a_frag = (wm + (lane & 15)) * 144 + (lane >> 4) * 16;
    const uint32_t b_frag = (lane & 15) * 272 + wn * 2 + (lane >> 4) * 16;

    auto issue = [&](int s) {
        const int k0 = s * 64;
        const uint32_t st = sb + (s % 3) * ST_STRIDE;
#pragma unroll
        for (int i = 0; i < 4; i++) {
            int c = tid + i * 256;
            int row = c >> 3, cc = c & 7;
            size_t g = (size_t)(m0 + row) * 2048 + k0 + cc * 8;
            cp16(st + row * 144 + cc * 16, A + g);
        }
#pragma unroll
        for (int i = 0; i < 4; i++) {
            int c = tid + i * 256;
            int row = c >> 4, cc = c & 15;
            size_t g = (size_t)(k0 + row) * 2048 + n0 + cc * 8;
            cp16(st + ST_W + row * 272 + cc * 16, W + g);
        }
    };

    issue(0); cp_commit();
    issue(1); cp_commit();

    const int NS = 32;
    for (int s = 0; s < NS; s++) {
        cp_wait<1>();
        __syncthreads();
        if (s + 2 < NS) issue(s + 2);
        cp_commit();

        const uint32_t base = sb + (s % 3) * ST_STRIDE;
        const uint32_t ab = base;
        const uint32_t wb = base + ST_W;

#pragma unroll
        for (int ks = 0; ks < 4; ks++) {
            uint32_t ah[4][4];
#pragma unroll
            for (int mt = 0; mt < 4; mt++)
                ldsm_x4(ah[mt], ab + a_frag + mt * 2304 + ks * 32);
            uint32_t bh[2][4];
#pragma unroll
            for (int np = 0; np < 2; np++)
                ldsm_x4_t(bh[np], wb + b_frag + ks * 4352 + np * 32);
#pragma unroll
            for (int mt = 0; mt < 4; mt++)
#pragma unroll
                for (int nt = 0; nt < 4; nt++)
                    mma_f16(acc[mt][nt], ah[mt], &bh[nt >> 1][(nt & 1) * 2]);
        }
    }

    // ---- epilogue ----
    const int lrow = lane >> 2;
    const int lcol = (lane & 3) * 2;
    const int h = blockIdx.x;
    const float QS = 0.0883883476483184405f * 1.4426950408889634f;

#pragma unroll
    for (int mt = 0; mt < 4; mt++) {
#pragma unroll
        for (int rh = 0; rh < 2; rh++) {
            const int m = m0 + wm + mt * 16 + lrow + rh * 8;
            if (!FUSED) {
                float* dst = Cout + (size_t)m * ND_ + n0;
#pragma unroll
                for (int nt = 0; nt < 4; nt++) {
                    int d = wn + nt * 8 + lcol;
                    *(float2*)(dst + d) = make_float2(acc[mt][nt][rh * 2 + 0],
                                                      acc[mt][nt][rh * 2 + 1]);
                }
            } else {
                const int b = m >> 11;
                const int t = m & (T_ - 1);
                const size_t rowoff = (((size_t)(b * H_ + h) * T_ + t) << 7);
                if (opz == 2) {
#pragma unroll
                    for (int nt = 0; nt < 4; nt++) {
                        int d = wn + nt * 8 + lcol;
                        *(uint32_t*)(gv + rowoff + d) =
                            pack_f16x2(acc[mt][nt][rh * 2 + 0], acc[mt][nt][rh * 2 + 1]);
                    }
                } else {
#pragma unroll
                    for (int nt = 0; nt < 4; nt++) {
                        int d = wn + nt * 8 + lcol;
                        float x0 = acc[mt][nt][rh * 2 + 0];
                        float x1 = acc[mt][nt][rh * 2 + 1];
                        float cs = g_cos[t * 64 + (d >> 1)];
                        float sn = g_sin[t * 64 + (d >> 1)];
                        float r0 = x0 * cs - x1 * sn;
                        float r1 = x0 * sn + x1 * cs;
                        if (opz == 0) {
                            *(uint32_t*)(gq + rowoff + d) = pack_f16x2(r0 * QS, r1 * QS);
                        } else {
                            *(uint32_t*)(gk + rowoff + d) = pack_f16x2(r0, r1);
                        }
                    }
                }
            }
        }
    }
}

__global__ void __launch_bounds__(256, 2) gemm_qkv_kernel() {
    gemm_body<1>((int)blockIdx.z, nullptr);
}
__global__ void __launch_bounds__(256, 2) gemm_o_kernel(float* __restrict__ Cout) {
    gemm_body<0>(3, Cout);
}

// ---------------------------------------------------------------------------
// Tensor-core flash attention: 1-term fp16 S and PV (Q, K, V single fp16).
// smem 104448 -> 2 CTAs/SM. Heavy-first remap; warp-level masked-tile skip;
// one __syncthreads per kv-tile.
// ---------------------------------------------------------------------------
#define KV_OFF 34816                 // Q: 128 * 272
#define KV_STRIDE 34816              // K + V, each 64*272 = 17408
#define KV_V 17408
#define ATT_SMEM (KV_OFF + 2 * KV_STRIDE)   // 104448

__global__ void __launch_bounds__(256, 2) attn_mma_kernel() {
    extern __shared__ char smc[];
    const uint32_t sb = smem_u32(smc);
    const int tid  = threadIdx.x;
    const int lane = tid & 31;
    const int wid  = tid >> 5;
    const int bh   = blockIdx.y;
    const int b    = bh >> 4;
    const int h    = bh & (H_ - 1);
    const int qt   = (int)(gridDim.x - 1) - blockIdx.x;   // heavy tiles first
    const int q0   = qt * 128;
    const int wm   = wid * 16;
    const int lrow = lane >> 2;
    const int lcol2 = (lane & 3) * 2;

    const __half* qg = gq + (size_t)bh * T_ * D_;
    const __half* kg = gk + (size_t)bh * T_ * D_;
    const __half* vg = gv + (size_t)bh * T_ * D_;

#pragma unroll
    for (int i = 0; i < 8; i++) {
        int c = tid + i * 256;
        int row = c >> 4, cc = c & 15;
        size_t g = (size_t)(q0 + row) * 128 + cc * 8;
        cp16(sb + row * 272 + cc * 16, qg + g);
    }
    cp_commit();

    auto issue_kv = [&](int buf, int k0) {
        uint32_t base = sb + KV_OFF + buf * KV_STRIDE;
#pragma unroll
        for (int i = 0; i < 4; i++) {
            int c = tid + i * 256;
            int row = c >> 4, cc = c & 15;
            size_t g = (size_t)(k0 + row) * 128 + cc * 8;
            uint32_t d = base + row * 272 + cc * 16;
            cp16(d, kg + g);
            cp16(d + KV_V, vg + g);
        }
    };

    issue_kv(0, 0);
    cp_commit();

    const uint32_t aq_frag = (wm + (lane & 15)) * 272 + (lane >> 4) * 16;
    const int kb_row = (lane & 7) + ((lane >> 4) << 3);
    const uint32_t kb_frag = kb_row * 272 + ((lane >> 3) & 1) * 16;
    const uint32_t vb_frag = (lane & 15) * 272 + (lane >> 4) * 16;

    float o[16][4];
#pragma unroll
    for (int dt = 0; dt < 16; dt++)
#pragma unroll
        for (int f = 0; f < 4; f++) o[dt][f] = 0.0f;
    float m0 = -1e30f, m1 = -1e30f, l0 = 0.0f, l1 = 0.0f;

    const int njt = 2 * qt + 2;

    for (int jt = 0; jt < njt; jt++) {
        cp_wait<0>();
        __syncthreads();
        if (jt + 1 < njt) issue_kv((jt + 1) & 1, (jt + 1) * 64);
        cp_commit();

        const int k0 = jt * 64;
        if (k0 <= q0 + wm + 15) {
            const uint32_t kvb = sb + KV_OFF + (jt & 1) * KV_STRIDE;
            const uint32_t aqh = sb + aq_frag;
            const uint32_t kbh = kvb + kb_frag;
            const uint32_t vbh = kvb + KV_V + vb_frag;

            // ---- S = Q K^T (1-term fp16, K fragments chunked for regs) ----
            float s[8][4];
#pragma unroll
            for (int nt = 0; nt < 8; nt++)
#pragma unroll
                for (int f = 0; f < 4; f++) s[nt][f] = 0.0f;

#pragma unroll
            for (int ks = 0; ks < 8; ks++) {
                uint32_t ah[4];
                ldsm_x4(ah, aqh + ks * 32);
#pragma unroll
                for (int half = 0; half < 2; half++) {
                    uint32_t kh[2][4];
#pragma unroll
                    for (int j = 0; j < 2; j++)
                        ldsm_x4(kh[j], kbh + (half * 2 + j) * 4352 + ks * 32);
#pragma unroll
                    for (int j = 0; j < 2; j++) {
                        int np = half * 2 + j;
                        mma_f16(s[2 * np],     ah, kh[j]);
                        mma_f16(s[2 * np + 1], ah, kh[j] + 2);
                    }
                }
            }

            if (k0 + 63 > q0 + wm) {
                const int row0 = q0 + wm + lrow;
                const int row1 = row0 + 8;
#pragma unroll
                for (int nt = 0; nt < 8; nt++) {
                    int c0 = k0 + nt * 8 + lcol2;
                    if (c0 > row0)     s[nt][0] = -1e30f;
                    if (c0 + 1 > row0) s[nt][1] = -1e30f;
                    if (c0 > row1)     s[nt][2] = -1e30f;
                    if (c0 + 1 > row1) s[nt][3] = -1e30f;
                }
            }

            float mx0 = -1e30f, mx1 = -1e30f;
#pragma unroll
            for (int nt = 0; nt < 8; nt++) {
                mx0 = fmaxf(mx0, fmaxf(s[nt][0], s[nt][1]));
                mx1 = fmaxf(mx1, fmaxf(s[nt][2], s[nt][3]));
            }
            mx0 = fmaxf(mx0, __shfl_xor_sync(0xffffffffu, mx0, 1));
            mx0 = fmaxf(mx0, __shfl_xor_sync(0xffffffffu, mx0, 2));
            mx1 = fmaxf(mx1, __shfl_xor_sync(0xffffffffu, mx1, 1));
            mx1 = fmaxf(mx1, __shfl_xor_sync(0xffffffffu, mx1, 2));
            float m0n = fmaxf(m0, mx0);
            float m1n = fmaxf(m1, mx1);
            float corr0 = exp2p(m0 - m0n);
            float corr1 = exp2p(m1 - m1n);
            m0 = m0n; m1 = m1n;

            uint32_t ph01[8], ph23[8];
            float sum0 = 0.0f, sum1 = 0.0f;
#pragma unroll
            for (int nt = 0; nt < 8; nt++) {
                float p0 = exp2p(s[nt][0] - m0);
                float p1 = exp2p(s[nt][1] - m0);
                float p2 = exp2p(s[nt][2] - m1);
                float p3 = exp2p(s[nt][3] - m1);
                sum0 += p0 + p1;
                sum1 += p2 + p3;
                ph01[nt] = pack_f16x2(p0, p1);
                ph23[nt] = pack_f16x2(p2, p3);
            }
            sum0 += __shfl_xor_sync(0xffffffffu, sum0, 1);
            sum0 += __shfl_xor_sync(0xffffffffu, sum0, 2);
            sum1 += __shfl_xor_sync(0xffffffffu, sum1, 1);
            sum1 += __shfl_xor_sync(0xffffffffu, sum1, 2);
            l0 = l0 * corr0 + sum0;
            l1 = l1 * corr1 + sum1;

#pragma unroll
            for (int dt = 0; dt < 16; dt++) {
                o[dt][0] *= corr0; o[dt][1] *= corr0;
                o[dt][2] *= corr1; o[dt][3] *= corr1;
            }

            // ---- O += P V (1-term fp16) ----
#pragma unroll
            for (int ks = 0; ks < 4; ks++) {
                uint32_t aph[4] = { ph01[2 * ks], ph23[2 * ks],
                                    ph01[2 * ks + 1], ph23[2 * ks + 1] };
#pragma unroll
                for (int half = 0; half < 2; half++) {
                    uint32_t vh[4][4];
#pragma unroll
                    for (int j = 0; j < 4; j++) {
                        int np = half * 4 + j;
                        ldsm_x4_t(vh[j], vbh + ks * 4352 + np * 32);
                    }
#pragma unroll
                    for (int j = 0; j < 4; j++) {
                        int np = half * 4 + j;
                        mma_f16(o[2 * np],     aph, vh[j]);
                        mma_f16(o[2 * np + 1], aph, vh[j] + 2);
                    }
                }
            }
        }
    }

    // ---- epilogue: normalize, store gao as single fp16 ----
    const float inv0 = 1.0f / l0;
    const float inv1 = 1.0f / l1;
    const int row0 = q0 + wm + lrow;
    const int row1 = row0 + 8;
    const size_t o0 = (size_t)(b * T_ + row0) * C_ + h * D_;
    const size_t o1 = (size_t)(b * T_ + row1) * C_ + h * D_;
#pragma unroll
    for (int dt = 0; dt < 16; dt++) {
        int d = dt * 8 + lcol2;
        *(uint32_t*)(gao + o0 + d) = pack_f16x2(o[dt][0] * inv0, o[dt][1] * inv0);
        *(uint32_t*)(gao + o1 + d) = pack_f16x2(o[dt][2] * inv1, o[dt][3] * inv1);
    }
}

// ---------------------------------------------------------------------------
// Launch
// ---------------------------------------------------------------------------
extern "C" void kernel_launch(void* const* d_in, const int* in_sizes, int n_in,
                              void* d_out, int out_size) {
    const float* x  = (const float*)d_in[0];
    const float* wq = (const float*)d_in[2];
    const float* wk = (const float*)d_in[3];
    const float* wv = (const float*)d_in[4];
    const float* wo = (const float*)d_in[5];
    float* out = (float*)d_out;

    rope_table_kernel<<<(T_ * (D_ / 2) + 255) / 256, 256>>>();

    const size_t total = NX_ + 4 * NW_;
    split_all_kernel<<<(unsigned)(total / 1024), 256>>>(x, wq, wk, wv, wo);

    cudaFuncSetAttribute(gemm_qkv_kernel, cudaFuncAttributeMaxDynamicSharedMemorySize, GEMM_SMEM);
    cudaFuncSetAttribute(gemm_o_kernel,   cudaFuncAttributeMaxDynamicSharedMemorySize, GEMM_SMEM);
    cudaFuncSetAttribute(attn_mma_kernel, cudaFuncAttributeMaxDynamicSharedMemorySize, ATT_SMEM);

    dim3 gqkv(ND_ / 128, M_ / 128, 3);   // (16, 32, 3) in ONE launch
    gemm_qkv_kernel<<<gqkv, 256, GEMM_SMEM>>>();

    attn_mma_kernel<<<dim3(T_ / 128, B_ * H_), 256, ATT_SMEM>>>();

    dim3 go(ND_ / 128, M_ / 128);        // (16, 32)
    gemm_o_kernel<<<go, 256, GEMM_SMEM>>>(out);
}